// round 1
// baseline (speedup 1.0000x reference)
#include <cuda_runtime.h>
#include <math.h>
#include <stdint.h>

#define BSZ   8192
#define TT    2
#define NF    40
#define DD    64
#define FEPS  1e-5f
#define CHUNK 4

// ---------------- device scratch (no allocations allowed) ----------------
__device__ float g_A [TT*NF*NF];          // attention matrices  (t,m,n)
__device__ float g_S [TT*NF*128];         // BN scale per (t,n,f)
__device__ float g_BP[TT*NF*DD];          // folded bias per (t,n,d)
__device__ float g_H [(size_t)BSZ*TT*NF*DD]; // h scratch (b,t,n,d)  168MB
__device__ float g_Wt[(size_t)BSZ*TT*NF];    // softmax weights (b,t,n)

// ---------------- prep 1: adjacency -> LN -> mask -> softmax -> A --------
__global__ void prep_adj(const float* __restrict__ masker,
                         const float* __restrict__ ln_gamma,
                         const float* __restrict__ ln_beta) {
    int t = blockIdx.x;
    __shared__ float sadj[NF*NF];
    int tid = threadIdx.x;
    const float* mk = masker + (size_t)t * 3 * NF * NF;
    for (int i = tid; i < NF*NF; i += blockDim.x) {
        float p = mk[i] * mk[NF*NF + i] * mk[2*NF*NF + i];
        sadj[i] = p > 0.f ? p : 0.f;
    }
    __syncthreads();
    if (tid < NF) {
        int j = tid;
        float sum = 0.f, sq = 0.f;
        for (int i = 0; i < NF; ++i) { float a = sadj[i*NF + j]; sum += a; sq += a*a; }
        float mu  = sum * (1.f/NF);
        float var = sq * (1.f/NF) - mu*mu;
        float rs  = rsqrtf(var + FEPS);
        float xm[NF];
        float mx = -1e30f;
        for (int i = 0; i < NF; ++i) {
            float a   = sadj[i*NF + j];
            float msk = (a != 0.f) ? 1.f : 0.f;
            float v   = (a - mu) * rs * ln_gamma[i] + ln_beta[i];
            v += (1.f - msk) * (-1e9f);
            if (i == j) v += 1.f;
            xm[i] = v;
            mx = fmaxf(mx, v);
        }
        float se = 0.f;
        for (int i = 0; i < NF; ++i) { xm[i] = expf(xm[i] - mx); se += xm[i]; }
        float inv = 1.f / se;
        for (int i = 0; i < NF; ++i) {
            float a   = sadj[i*NF + j];
            float msk = (a != 0.f) ? 1.f : 0.f;
            g_A[t*NF*NF + i*NF + j] = xm[i] * inv * msk;
        }
    }
}

// ---------------- prep 2: fold BN into scale s and bias b' ---------------
__global__ void prep_sbp(const float* __restrict__ bn_gamma,
                         const float* __restrict__ bn_beta,
                         const float* __restrict__ bn_mean,
                         const float* __restrict__ bn_var,
                         const float* __restrict__ gnn_w,
                         const float* __restrict__ gnn_b) {
    int blk = blockIdx.x;          // t*40 + n
    int t = blk / NF, n = blk - t*NF;
    __shared__ float so[128];
    int tid = threadIdx.x;         // 128 threads
    int F = blk*128 + tid;
    float s = bn_gamma[F] * rsqrtf(bn_var[F] + FEPS);
    float o = bn_beta[F] - bn_mean[F] * s;
    g_S[blk*128 + tid] = s;
    so[tid] = o;
    __syncthreads();
    if (tid < DD) {
        float acc = gnn_b[t*NF*DD + n*DD + tid];
        #pragma unroll 8
        for (int f = 0; f < 128; ++f)
            acc += so[f] * gnn_w[t*128*DD + f*DD + tid];
        g_BP[blk*DD + tid] = acc;
    }
}

// ---------------- kernel 1: nei + scaled GNN transform -> h --------------
// dynamic smem layout (floats):
//  sA   [2][40][40]   @ 0       (3200)
//  sW   [2][128][64]  @ 3200    (16384)
//  sS   [2][40][128]  @ 19584   (10240)
//  sX   [4][40][64]   @ 29824   (10240)
//  sNei [4][40][64]   @ 40064   (10240)
//  sROW [8][4][128]   @ 50304   (4096)
// total 54400 floats = 217600 B
#define SMEM1_FLOATS 54400
__global__ __launch_bounds__(256, 1)
void k_forward(const float* __restrict__ x, const float* __restrict__ gnn_w) {
    extern __shared__ float sm[];
    float* sA   = sm;
    float* sW   = sm + 3200;
    float* sS   = sm + 19584;
    float* sX   = sm + 29824;
    float* sNei = sm + 40064;
    float* sROW = sm + 50304;

    int tid  = threadIdx.x;
    int wid  = tid >> 5;
    int lane = tid & 31;
    int b0   = blockIdx.x * CHUNK;

    for (int i = tid; i < 3200;  i += 256) sA[i] = g_A[i];
    for (int i = tid; i < 16384; i += 256) sW[i] = gnn_w[i];
    for (int i = tid; i < 10240; i += 256) sS[i] = g_S[i];
    const float* xb = x + (size_t)b0 * NF * DD;
    for (int i = tid; i < 10240; i += 256) sX[i] = xb[i];
    __syncthreads();

    for (int t = 0; t < TT; ++t) {
        // ---- phase A: nei[c][n][d] = sum_m A[t][m][n] * x[c][m][d] ----
        const float* At = sA + t * NF * NF;
        for (int tile = tid; tile < 640; tile += 256) {
            int c  = tile / 160;
            int r  = tile - c * 160;
            int ng = r >> 4;     // n-group of 4
            int dg = r & 15;     // d-group of 4
            float4 a0 = {0,0,0,0}, a1 = a0, a2 = a0, a3 = a0;
            const float* xp = sX + c*2560 + dg*4;
            const float* ap = At + ng*4;
            #pragma unroll 5
            for (int m = 0; m < NF; ++m) {
                float4 xv = *(const float4*)(xp + m*64);
                float4 av = *(const float4*)(ap + m*NF);
                a0.x += av.x*xv.x; a0.y += av.x*xv.y; a0.z += av.x*xv.z; a0.w += av.x*xv.w;
                a1.x += av.y*xv.x; a1.y += av.y*xv.y; a1.z += av.y*xv.z; a1.w += av.y*xv.w;
                a2.x += av.z*xv.x; a2.y += av.z*xv.y; a2.z += av.z*xv.z; a2.w += av.z*xv.w;
                a3.x += av.w*xv.x; a3.y += av.w*xv.y; a3.z += av.w*xv.z; a3.w += av.w*xv.w;
            }
            float* np = sNei + c*2560 + (ng*4)*64 + dg*4;
            *(float4*)(np)        = a0;
            *(float4*)(np + 64)   = a1;
            *(float4*)(np + 128)  = a2;
            *(float4*)(np + 192)  = a3;
        }
        __syncthreads();

        // ---- phase B: h[row] = (xcat * s) @ W[t] + b'  (row = c*40+n) ----
        float* rowbuf = sROW + wid * 512;
        const float* Wt = sW + t*8192 + lane*2;
        for (int g = wid; g < 40; g += 8) {
            int rbase = g * 4;
            #pragma unroll
            for (int j = 0; j < 4; ++j) {
                int row = rbase + j;
                int c = row / 40;
                int n = row - c * 40;
                const float* sp = sS + t*5120 + n*128;
                const float* xp = sX + c*2560 + n*64;
                const float* np = sNei + c*2560 + n*64;
                rowbuf[j*128 + lane]      = xp[lane]      * sp[lane];
                rowbuf[j*128 + lane + 32] = xp[lane + 32] * sp[lane + 32];
                rowbuf[j*128 + lane + 64] = np[lane]      * sp[lane + 64];
                rowbuf[j*128 + lane + 96] = np[lane + 32] * sp[lane + 96];
            }
            __syncwarp();

            float2 acc0 = {0,0}, acc1 = {0,0}, acc2 = {0,0}, acc3 = {0,0};
            #pragma unroll 4
            for (int f0 = 0; f0 < 128; f0 += 4) {
                float4 r0 = *(const float4*)(rowbuf +        f0);
                float4 r1 = *(const float4*)(rowbuf + 128 +  f0);
                float4 r2 = *(const float4*)(rowbuf + 256 +  f0);
                float4 r3 = *(const float4*)(rowbuf + 384 +  f0);
                float ra[4] = {r0.x, r0.y, r0.z, r0.w};
                float rb[4] = {r1.x, r1.y, r1.z, r1.w};
                float rc[4] = {r2.x, r2.y, r2.z, r2.w};
                float rd[4] = {r3.x, r3.y, r3.z, r3.w};
                #pragma unroll
                for (int ff = 0; ff < 4; ++ff) {
                    float2 w = *(const float2*)(Wt + (f0 + ff)*64);
                    acc0.x += ra[ff]*w.x; acc0.y += ra[ff]*w.y;
                    acc1.x += rb[ff]*w.x; acc1.y += rb[ff]*w.y;
                    acc2.x += rc[ff]*w.x; acc2.y += rc[ff]*w.y;
                    acc3.x += rd[ff]*w.x; acc3.y += rd[ff]*w.y;
                }
            }
            __syncwarp();

            float2 accs[4] = {acc0, acc1, acc2, acc3};
            #pragma unroll
            for (int j = 0; j < 4; ++j) {
                int row = rbase + j;
                int c = row / 40;
                int n = row - c * 40;
                int b = b0 + c;
                float2 bp = *(const float2*)(g_BP + t*2560 + n*64 + lane*2);
                float2 o;
                o.x = accs[j].x + bp.x;
                o.y = accs[j].y + bp.y;
                float* hp = g_H + ((((size_t)b*TT + t)*NF + n) * DD) + lane*2;
                *(float2*)hp = o;
            }
        }
        __syncthreads();
    }
}

// ---------------- kernel 2: gate GEMM + row softmax -> w -----------------
// M = 16384 rows (b,t), K = 2560, N = 40. Mtile = 128, Ktile = 64.
__global__ __launch_bounds__(256)
void k_gate(const float* __restrict__ gate_w, const float* __restrict__ gate_b) {
    __shared__ float sHt[128 * 65];   // padded stride 65
    __shared__ float sGt[64 * 41];    // padded stride 41
    int tid  = threadIdx.x;
    int row0 = blockIdx.x * 128;
    int rg = tid >> 3;   // 0..31 -> 4 rows each
    int cg = tid & 7;    // 0..7  -> 5 cols each
    float acc[4][5];
    #pragma unroll
    for (int i = 0; i < 4; ++i)
        #pragma unroll
        for (int j = 0; j < 5; ++j) acc[i][j] = 0.f;

    for (int k0 = 0; k0 < 2560; k0 += 64) {
        for (int idx = tid; idx < 128*64; idx += 256) {
            int r = idx >> 6, k = idx & 63;
            sHt[r*65 + k] = g_H[(size_t)(row0 + r) * 2560 + k0 + k];
        }
        for (int idx = tid; idx < 64*40; idx += 256) {
            int k = idx / 40, c = idx - k*40;
            sGt[k*41 + c] = gate_w[(k0 + k)*40 + c];
        }
        __syncthreads();
        #pragma unroll 4
        for (int k = 0; k < 64; ++k) {
            float hv[4], gv[5];
            #pragma unroll
            for (int i = 0; i < 4; ++i) hv[i] = sHt[(rg*4 + i)*65 + k];
            #pragma unroll
            for (int j = 0; j < 5; ++j) gv[j] = sGt[k*41 + cg*5 + j];
            #pragma unroll
            for (int i = 0; i < 4; ++i)
                #pragma unroll
                for (int j = 0; j < 5; ++j) acc[i][j] += hv[i]*gv[j];
        }
        __syncthreads();
    }

    // logits -> smem (reuse sHt, stride 41), add bias
    #pragma unroll
    for (int i = 0; i < 4; ++i)
        #pragma unroll
        for (int j = 0; j < 5; ++j)
            sHt[(rg*4 + i)*41 + cg*5 + j] = acc[i][j] + gate_b[cg*5 + j];
    __syncthreads();

    if (tid < 128) {
        int row = tid;
        float mx = -1e30f;
        #pragma unroll 8
        for (int n = 0; n < 40; ++n) mx = fmaxf(mx, sHt[row*41 + n]);
        float se = 0.f;
        #pragma unroll 8
        for (int n = 0; n < 40; ++n) se += expf(sHt[row*41 + n] - mx);
        float inv = 1.f / se;
        float* wp = g_Wt + (size_t)(row0 + row) * 40;
        #pragma unroll 8
        for (int n = 0; n < 40; ++n) wp[n] = expf(sHt[row*41 + n] - mx) * inv;
    }
}

// ---------------- kernel 3: weighted pool -> out --------------------------
__global__ __launch_bounds__(256)
void k_pool(float* __restrict__ out) {
    int wid = threadIdx.x >> 5, lane = threadIdx.x & 31;
    size_t row = (size_t)blockIdx.x * 8 + wid;   // (b*2+t), 0..16383
    const float* hp = g_H  + row * 2560;
    const float* wp = g_Wt + row * 40;
    float a0 = 0.f, a1 = 0.f;
    #pragma unroll 8
    for (int n = 0; n < 40; ++n) {
        float w = wp[n];
        a0 += w * hp[n*64 + lane];
        a1 += w * hp[n*64 + lane + 32];
    }
    out[row*64 + lane]      = a0;
    out[row*64 + lane + 32] = a1;
}

// ---------------- launcher ------------------------------------------------
extern "C" void kernel_launch(void* const* d_in, const int* in_sizes, int n_in,
                              void* d_out, int out_size) {
    const float* x        = (const float*)d_in[0];
    const float* masker   = (const float*)d_in[1];
    const float* ln_gamma = (const float*)d_in[2];
    const float* ln_beta  = (const float*)d_in[3];
    const float* gnn_w    = (const float*)d_in[4];
    const float* gnn_b    = (const float*)d_in[5];
    const float* bn_gamma = (const float*)d_in[6];
    const float* bn_beta  = (const float*)d_in[7];
    const float* bn_mean  = (const float*)d_in[8];
    const float* bn_var   = (const float*)d_in[9];
    const float* gate_w   = (const float*)d_in[10];
    const float* gate_b   = (const float*)d_in[11];
    float* out = (float*)d_out;

    cudaFuncSetAttribute(k_forward, cudaFuncAttributeMaxDynamicSharedMemorySize,
                         SMEM1_FLOATS * (int)sizeof(float));

    prep_adj<<<2, 256>>>(masker, ln_gamma, ln_beta);
    prep_sbp<<<80, 128>>>(bn_gamma, bn_beta, bn_mean, bn_var, gnn_w, gnn_b);
    k_forward<<<BSZ / CHUNK, 256, SMEM1_FLOATS * sizeof(float)>>>(x, gnn_w);
    k_gate<<<BSZ * TT / 128, 256>>>(gate_w, gate_b);
    k_pool<<<BSZ * TT / 8, 256>>>(out);
}

// round 3
// speedup vs baseline: 1.1327x; 1.1327x over previous
#include <cuda_runtime.h>
#include <math.h>
#include <stdint.h>

#define BSZ   8192
#define TT    2
#define NF    40
#define DD    64
#define FEPS  1e-5f
#define CHUNK 4

// ---------------- device scratch (no allocations allowed) ----------------
__device__ float g_A [TT*NF*NF];          // attention matrices  (t,m,n)
__device__ float g_S [TT*NF*128];         // BN scale per (t,n,f)
__device__ float g_BP[TT*NF*DD];          // folded bias per (t,n,d)
__device__ float g_H [(size_t)BSZ*TT*NF*DD]; // h scratch (b,t,n,d)  168MB
__device__ float g_GT[NF*NF*DD];          // gate_w transposed: [n'][k] 40x2560

// ---------------- prep 1: adjacency -> LN -> mask -> softmax -> A --------
__global__ void prep_adj(const float* __restrict__ masker,
                         const float* __restrict__ ln_gamma,
                         const float* __restrict__ ln_beta) {
    int t = blockIdx.x;
    __shared__ float sadj[NF*NF];
    int tid = threadIdx.x;
    const float* mk = masker + (size_t)t * 3 * NF * NF;
    for (int i = tid; i < NF*NF; i += blockDim.x) {
        float p = mk[i] * mk[NF*NF + i] * mk[2*NF*NF + i];
        sadj[i] = p > 0.f ? p : 0.f;
    }
    __syncthreads();
    if (tid < NF) {
        int j = tid;
        float sum = 0.f, sq = 0.f;
        for (int i = 0; i < NF; ++i) { float a = sadj[i*NF + j]; sum += a; sq += a*a; }
        float mu  = sum * (1.f/NF);
        float var = sq * (1.f/NF) - mu*mu;
        float rs  = rsqrtf(var + FEPS);
        float xm[NF];
        float mx = -1e30f;
        for (int i = 0; i < NF; ++i) {
            float a   = sadj[i*NF + j];
            float msk = (a != 0.f) ? 1.f : 0.f;
            float v   = (a - mu) * rs * ln_gamma[i] + ln_beta[i];
            v += (1.f - msk) * (-1e9f);
            if (i == j) v += 1.f;
            xm[i] = v;
            mx = fmaxf(mx, v);
        }
        float se = 0.f;
        for (int i = 0; i < NF; ++i) { xm[i] = expf(xm[i] - mx); se += xm[i]; }
        float inv = 1.f / se;
        for (int i = 0; i < NF; ++i) {
            float a   = sadj[i*NF + j];
            float msk = (a != 0.f) ? 1.f : 0.f;
            g_A[t*NF*NF + i*NF + j] = xm[i] * inv * msk;
        }
    }
}

// ---------------- prep 2: fold BN into scale s and bias b' ---------------
__global__ void prep_sbp(const float* __restrict__ bn_gamma,
                         const float* __restrict__ bn_beta,
                         const float* __restrict__ bn_mean,
                         const float* __restrict__ bn_var,
                         const float* __restrict__ gnn_w,
                         const float* __restrict__ gnn_b) {
    int blk = blockIdx.x;          // t*40 + n
    int t = blk / NF, n = blk - t*NF;
    __shared__ float so[128];
    int tid = threadIdx.x;         // 128 threads
    int F = blk*128 + tid;
    float s = bn_gamma[F] * rsqrtf(bn_var[F] + FEPS);
    float o = bn_beta[F] - bn_mean[F] * s;
    g_S[blk*128 + tid] = s;
    so[tid] = o;
    __syncthreads();
    if (tid < DD) {
        float acc = gnn_b[t*NF*DD + n*DD + tid];
        #pragma unroll 8
        for (int f = 0; f < 128; ++f)
            acc += so[f] * gnn_w[t*128*DD + f*DD + tid];
        g_BP[blk*DD + tid] = acc;
    }
}

// ---------------- prep 3: transpose gate_w -> g_GT [n'][k] --------------
__global__ void prep_gt(const float* __restrict__ gate_w) {
    int i = blockIdx.x * 256 + threadIdx.x;  // i = c*2560 + k
    if (i < NF * 2560) {
        int c = i / 2560;
        int k = i - c * 2560;
        g_GT[i] = gate_w[k * NF + c];
    }
}

// ---------------- kernel 1: nei + scaled GNN transform -> h --------------
// dynamic smem layout (floats):
//  sA   [2][40][40]   @ 0       (3200)
//  sW   [2][128][64]  @ 3200    (16384)
//  sS   [2][40][128]  @ 19584   (10240)
//  sX   [4][40][64]   @ 29824   (10240)
//  sNei [4][40][64]   @ 40064   (10240)
//  sROW [8][4][128]   @ 50304   (4096)
// total 54400 floats = 217600 B
#define SMEM1_FLOATS 54400
__global__ __launch_bounds__(256, 1)
void k_forward(const float* __restrict__ x, const float* __restrict__ gnn_w) {
    extern __shared__ float sm[];
    float* sA   = sm;
    float* sW   = sm + 3200;
    float* sS   = sm + 19584;
    float* sX   = sm + 29824;
    float* sNei = sm + 40064;
    float* sROW = sm + 50304;

    int tid  = threadIdx.x;
    int wid  = tid >> 5;
    int lane = tid & 31;
    int b0   = blockIdx.x * CHUNK;

    for (int i = tid; i < 3200;  i += 256) sA[i] = g_A[i];
    for (int i = tid; i < 16384; i += 256) sW[i] = gnn_w[i];
    for (int i = tid; i < 10240; i += 256) sS[i] = g_S[i];
    const float* xb = x + (size_t)b0 * NF * DD;
    for (int i = tid; i < 10240; i += 256) sX[i] = xb[i];
    __syncthreads();

    for (int t = 0; t < TT; ++t) {
        // ---- phase A: nei[c][n][d] = sum_m A[t][m][n] * x[c][m][d] ----
        const float* At = sA + t * NF * NF;
        for (int tile = tid; tile < 640; tile += 256) {
            int c  = tile / 160;
            int r  = tile - c * 160;
            int ng = r >> 4;     // n-group of 4
            int dg = r & 15;     // d-group of 4
            float4 a0 = {0,0,0,0}, a1 = a0, a2 = a0, a3 = a0;
            const float* xp = sX + c*2560 + dg*4;
            const float* ap = At + ng*4;
            #pragma unroll 5
            for (int m = 0; m < NF; ++m) {
                float4 xv = *(const float4*)(xp + m*64);
                float4 av = *(const float4*)(ap + m*NF);
                a0.x += av.x*xv.x; a0.y += av.x*xv.y; a0.z += av.x*xv.z; a0.w += av.x*xv.w;
                a1.x += av.y*xv.x; a1.y += av.y*xv.y; a1.z += av.y*xv.z; a1.w += av.y*xv.w;
                a2.x += av.z*xv.x; a2.y += av.z*xv.y; a2.z += av.z*xv.z; a2.w += av.z*xv.w;
                a3.x += av.w*xv.x; a3.y += av.w*xv.y; a3.z += av.w*xv.z; a3.w += av.w*xv.w;
            }
            float* np = sNei + c*2560 + (ng*4)*64 + dg*4;
            *(float4*)(np)        = a0;
            *(float4*)(np + 64)   = a1;
            *(float4*)(np + 128)  = a2;
            *(float4*)(np + 192)  = a3;
        }
        __syncthreads();

        // ---- phase B: h[row] = (xcat * s) @ W[t] + b'  (row = c*40+n) ----
        float* rowbuf = sROW + wid * 512;
        const float* Wt = sW + t*8192 + lane*2;
        for (int g = wid; g < 40; g += 8) {
            int rbase = g * 4;
            #pragma unroll
            for (int j = 0; j < 4; ++j) {
                int row = rbase + j;
                int c = row / 40;
                int n = row - c * 40;
                const float* sp = sS + t*5120 + n*128;
                const float* xp = sX + c*2560 + n*64;
                const float* np = sNei + c*2560 + n*64;
                rowbuf[j*128 + lane]      = xp[lane]      * sp[lane];
                rowbuf[j*128 + lane + 32] = xp[lane + 32] * sp[lane + 32];
                rowbuf[j*128 + lane + 64] = np[lane]      * sp[lane + 64];
                rowbuf[j*128 + lane + 96] = np[lane + 32] * sp[lane + 96];
            }
            __syncwarp();

            float2 acc0 = {0,0}, acc1 = {0,0}, acc2 = {0,0}, acc3 = {0,0};
            #pragma unroll 4
            for (int f0 = 0; f0 < 128; f0 += 4) {
                float4 r0 = *(const float4*)(rowbuf +        f0);
                float4 r1 = *(const float4*)(rowbuf + 128 +  f0);
                float4 r2 = *(const float4*)(rowbuf + 256 +  f0);
                float4 r3 = *(const float4*)(rowbuf + 384 +  f0);
                float ra[4] = {r0.x, r0.y, r0.z, r0.w};
                float rb[4] = {r1.x, r1.y, r1.z, r1.w};
                float rc[4] = {r2.x, r2.y, r2.z, r2.w};
                float rd[4] = {r3.x, r3.y, r3.z, r3.w};
                #pragma unroll
                for (int ff = 0; ff < 4; ++ff) {
                    float2 w = *(const float2*)(Wt + (f0 + ff)*64);
                    acc0.x += ra[ff]*w.x; acc0.y += ra[ff]*w.y;
                    acc1.x += rb[ff]*w.x; acc1.y += rb[ff]*w.y;
                    acc2.x += rc[ff]*w.x; acc2.y += rc[ff]*w.y;
                    acc3.x += rd[ff]*w.x; acc3.y += rd[ff]*w.y;
                }
            }
            __syncwarp();

            float2 accs[4] = {acc0, acc1, acc2, acc3};
            #pragma unroll
            for (int j = 0; j < 4; ++j) {
                int row = rbase + j;
                int c = row / 40;
                int n = row - c * 40;
                int b = b0 + c;
                float2 bp = *(const float2*)(g_BP + t*2560 + n*64 + lane*2);
                float2 o;
                o.x = accs[j].x + bp.x;
                o.y = accs[j].y + bp.y;
                float* hp = g_H + ((((size_t)b*TT + t)*NF + n) * DD) + lane*2;
                *(float2*)hp = o;
            }
        }
        __syncthreads();
    }
}

// ---------------- kernel 2: gate GEMM + softmax + pooled output ----------
// M = 16384 rows (b,t), K = 2560, N = 40. M-tile = 64 -> grid 256.
// Register blocking 4 rows x 5 cols per thread, float4 over K.
// Smem row stride 68 floats = 272B (16B aligned for LDS128).
// After softmax, pool re-reads the h tile (L2-hot) and writes out directly.
#define GT_TM 64
#define GSTR  68
__global__ __launch_bounds__(128)
void k_gate(const float* __restrict__ gate_b, float* __restrict__ out) {
    __shared__ float sH[GT_TM * GSTR];   // h tile [row][k]
    __shared__ float sG[NF * GSTR];      // gate  [col][k]
    int tid  = threadIdx.x;
    int row0 = blockIdx.x * GT_TM;
    int rg = tid >> 3;   // 0..15 -> 4 rows each
    int cg = tid & 7;    // 0..7  -> 5 cols each

    float acc[4][5];
    #pragma unroll
    for (int i = 0; i < 4; ++i)
        #pragma unroll
        for (int j = 0; j < 5; ++j) acc[i][j] = 0.f;

    for (int k0 = 0; k0 < 2560; k0 += 64) {
        for (int idx = tid; idx < 1024; idx += 128) {
            int r = idx >> 4, kq = idx & 15;
            *(float4*)(sH + r*GSTR + kq*4) =
                *(const float4*)(g_H + (size_t)(row0 + r)*2560 + k0 + kq*4);
        }
        for (int idx = tid; idx < 640; idx += 128) {
            int c = idx >> 4, kq = idx & 15;
            *(float4*)(sG + c*GSTR + kq*4) =
                *(const float4*)(g_GT + (size_t)c*2560 + k0 + kq*4);
        }
        __syncthreads();
        #pragma unroll
        for (int k4 = 0; k4 < 16; ++k4) {
            float4 hv[4], gv[5];
            #pragma unroll
            for (int i = 0; i < 4; ++i)
                hv[i] = *(const float4*)(sH + (rg*4 + i)*GSTR + k4*4);
            #pragma unroll
            for (int j = 0; j < 5; ++j)
                gv[j] = *(const float4*)(sG + (cg*5 + j)*GSTR + k4*4);
            #pragma unroll
            for (int i = 0; i < 4; ++i)
                #pragma unroll
                for (int j = 0; j < 5; ++j) {
                    acc[i][j] += hv[i].x * gv[j].x;
                    acc[i][j] += hv[i].y * gv[j].y;
                    acc[i][j] += hv[i].z * gv[j].z;
                    acc[i][j] += hv[i].w * gv[j].w;
                }
        }
        __syncthreads();
    }

    // logits -> smem (reuse sH as [64][41], scalar stores)
    #pragma unroll
    for (int i = 0; i < 4; ++i)
        #pragma unroll
        for (int j = 0; j < 5; ++j)
            sH[(rg*4 + i)*41 + cg*5 + j] = acc[i][j] + __ldg(gate_b + cg*5 + j);
    __syncthreads();

    // per-row softmax, weights written back in place
    if (tid < GT_TM) {
        float* lp = sH + tid*41;
        float mx = -1e30f;
        #pragma unroll 8
        for (int n = 0; n < NF; ++n) mx = fmaxf(mx, lp[n]);
        float se = 0.f;
        #pragma unroll 8
        for (int n = 0; n < NF; ++n) se += expf(lp[n] - mx);
        float inv = 1.f / se;
        #pragma unroll 8
        for (int n = 0; n < NF; ++n) lp[n] = expf(lp[n] - mx) * inv;
    }
    __syncthreads();

    // pool: out[row, d] = sum_n w[row,n] * h[row, n*64+d]   (h tile L2-hot)
    {
        int row = tid >> 1;
        int off = (tid & 1) * 32;
        const float* hp = g_H + (size_t)(row0 + row)*2560 + off;
        const float* wp = sH + row*41;
        float4 a[8];
        #pragma unroll
        for (int q = 0; q < 8; ++q) a[q] = make_float4(0.f, 0.f, 0.f, 0.f);
        #pragma unroll 4
        for (int n = 0; n < NF; ++n) {
            float wv = wp[n];
            const float4* h4 = (const float4*)(hp + n*64);
            #pragma unroll
            for (int q = 0; q < 8; ++q) {
                float4 hv = h4[q];
                a[q].x += wv * hv.x;
                a[q].y += wv * hv.y;
                a[q].z += wv * hv.z;
                a[q].w += wv * hv.w;
            }
        }
        float* op = out + (size_t)(row0 + row)*64 + off;
        #pragma unroll
        for (int q = 0; q < 8; ++q) *(float4*)(op + q*4) = a[q];
    }
}

// ---------------- launcher ------------------------------------------------
extern "C" void kernel_launch(void* const* d_in, const int* in_sizes, int n_in,
                              void* d_out, int out_size) {
    const float* x        = (const float*)d_in[0];
    const float* masker   = (const float*)d_in[1];
    const float* ln_gamma = (const float*)d_in[2];
    const float* ln_beta  = (const float*)d_in[3];
    const float* gnn_w    = (const float*)d_in[4];
    const float* gnn_b    = (const float*)d_in[5];
    const float* bn_gamma = (const float*)d_in[6];
    const float* bn_beta  = (const float*)d_in[7];
    const float* bn_mean  = (const float*)d_in[8];
    const float* bn_var   = (const float*)d_in[9];
    const float* gate_w   = (const float*)d_in[10];
    const float* gate_b   = (const float*)d_in[11];
    float* out = (float*)d_out;

    cudaFuncSetAttribute(k_forward, cudaFuncAttributeMaxDynamicSharedMemorySize,
                         SMEM1_FLOATS * (int)sizeof(float));

    prep_adj<<<2, 256>>>(masker, ln_gamma, ln_beta);
    prep_sbp<<<80, 128>>>(bn_gamma, bn_beta, bn_mean, bn_var, gnn_w, gnn_b);
    prep_gt<<<(NF*2560 + 255)/256, 256>>>(gate_w);
    k_forward<<<BSZ / CHUNK, 256, SMEM1_FLOATS * sizeof(float)>>>(x, gnn_w);
    k_gate<<<BSZ * TT / GT_TM, 128>>>(gate_b, out);
}

// round 4
// speedup vs baseline: 1.4080x; 1.2431x over previous
#include <cuda_runtime.h>
#include <math.h>
#include <stdint.h>

#define BSZ   8192
#define TT    2
#define NF    40
#define DD    64
#define FEPS  1e-5f
#define CHUNK 4

// ---------------- device scratch (no allocations allowed) ----------------
__device__ float g_A [TT*NF*NF];          // attention matrices  (t,m,n)
__device__ float g_S [TT*NF*128];         // BN scale per (t,n,f)
__device__ float g_BP[TT*NF*DD];          // folded bias per (t,n,d)
__device__ float g_H [(size_t)BSZ*TT*NF*DD]; // h scratch (b,t,n,d)  168MB
__device__ float g_GT[NF*NF*DD];          // gate_w transposed: [n'][k] 40x2560

// ---------------- prep 1: adjacency -> LN -> mask -> softmax -> A --------
__global__ void prep_adj(const float* __restrict__ masker,
                         const float* __restrict__ ln_gamma,
                         const float* __restrict__ ln_beta) {
    int t = blockIdx.x;
    __shared__ float sadj[NF*NF];
    int tid = threadIdx.x;
    const float* mk = masker + (size_t)t * 3 * NF * NF;
    for (int i = tid; i < NF*NF; i += blockDim.x) {
        float p = mk[i] * mk[NF*NF + i] * mk[2*NF*NF + i];
        sadj[i] = p > 0.f ? p : 0.f;
    }
    __syncthreads();
    if (tid < NF) {
        int j = tid;
        float sum = 0.f, sq = 0.f;
        for (int i = 0; i < NF; ++i) { float a = sadj[i*NF + j]; sum += a; sq += a*a; }
        float mu  = sum * (1.f/NF);
        float var = sq * (1.f/NF) - mu*mu;
        float rs  = rsqrtf(var + FEPS);
        float xm[NF];
        float mx = -1e30f;
        for (int i = 0; i < NF; ++i) {
            float a   = sadj[i*NF + j];
            float msk = (a != 0.f) ? 1.f : 0.f;
            float v   = (a - mu) * rs * ln_gamma[i] + ln_beta[i];
            v += (1.f - msk) * (-1e9f);
            if (i == j) v += 1.f;
            xm[i] = v;
            mx = fmaxf(mx, v);
        }
        float se = 0.f;
        for (int i = 0; i < NF; ++i) { xm[i] = expf(xm[i] - mx); se += xm[i]; }
        float inv = 1.f / se;
        for (int i = 0; i < NF; ++i) {
            float a   = sadj[i*NF + j];
            float msk = (a != 0.f) ? 1.f : 0.f;
            g_A[t*NF*NF + i*NF + j] = xm[i] * inv * msk;
        }
    }
}

// ---------------- prep 2: fold BN into scale s and bias b' ---------------
__global__ void prep_sbp(const float* __restrict__ bn_gamma,
                         const float* __restrict__ bn_beta,
                         const float* __restrict__ bn_mean,
                         const float* __restrict__ bn_var,
                         const float* __restrict__ gnn_w,
                         const float* __restrict__ gnn_b) {
    int blk = blockIdx.x;          // t*40 + n
    int t = blk / NF, n = blk - t*NF;
    __shared__ float so[128];
    int tid = threadIdx.x;         // 128 threads
    int F = blk*128 + tid;
    float s = bn_gamma[F] * rsqrtf(bn_var[F] + FEPS);
    float o = bn_beta[F] - bn_mean[F] * s;
    g_S[blk*128 + tid] = s;
    so[tid] = o;
    __syncthreads();
    if (tid < DD) {
        float acc = gnn_b[t*NF*DD + n*DD + tid];
        #pragma unroll 8
        for (int f = 0; f < 128; ++f)
            acc += so[f] * gnn_w[t*128*DD + f*DD + tid];
        g_BP[blk*DD + tid] = acc;
    }
}

// ---------------- prep 3: transpose gate_w -> g_GT [n'][k] --------------
__global__ void prep_gt(const float* __restrict__ gate_w) {
    int i = blockIdx.x * 256 + threadIdx.x;  // i = c*2560 + k
    if (i < NF * 2560) {
        int c = i / 2560;
        int k = i - c * 2560;
        g_GT[i] = gate_w[k * NF + c];
    }
}

// ---------------- kernel 1: nei + scaled GNN transform -> h --------------
// smem (floats):
//  sA   [2][40][40]      @ 0       (3200)
//  sW   [2][128][64]     @ 3200    (16384)
//  sX   [4][40][64]      @ 19584   (10240)
//  sCat [160][132]       @ 29824   (21120)   (stride 132 = conflict-free)
// total 50944 floats = 203776 B
#define SMEM1_FLOATS 50944
#define CSTR 132
__global__ __launch_bounds__(256, 1)
void k_forward(const float* __restrict__ x, const float* __restrict__ gnn_w) {
    extern __shared__ float sm[];
    float* sA   = sm;
    float* sW   = sm + 3200;
    float* sX   = sm + 19584;
    float* sCat = sm + 29824;

    int tid  = threadIdx.x;
    int b0   = blockIdx.x * CHUNK;

    for (int i = tid; i < 3200;  i += 256) sA[i] = g_A[i];
    for (int i = tid; i < 16384; i += 256) sW[i] = gnn_w[i];
    const float* xb = x + (size_t)b0 * NF * DD;
    for (int i = tid; i < 10240; i += 256) sX[i] = xb[i];
    __syncthreads();

    int rg = tid >> 3;    // 0..31 -> 5 rows each
    int cg = tid & 7;     // 0..7  -> 8 cols each

    for (int t = 0; t < TT; ++t) {
        const float* St = g_S + t * NF * 128;

        // ---- lower half of sCat: x * s_lo  (vectorized) ----
        for (int i = tid; i < 2560; i += 256) {      // i indexes float4
            int row = i >> 4;                         // 16 float4 per row
            int dq  = (i & 15) * 4;
            int n   = row - (row / 40) * 40;
            float4 xv = *(const float4*)(sX + row*64 + dq);
            float4 sv = __ldg((const float4*)(St + n*128 + dq));
            xv.x *= sv.x; xv.y *= sv.y; xv.z *= sv.z; xv.w *= sv.w;
            *(float4*)(sCat + row*CSTR + dq) = xv;
        }

        // ---- upper half: nei * s_hi  (phase A with fused scale) ----
        const float* At = sA + t * NF * NF;
        for (int tile = tid; tile < 640; tile += 256) {
            int c  = tile / 160;
            int r  = tile - c * 160;
            int ng = r >> 4;     // n-group of 4
            int dg = r & 15;     // d-group of 4
            float4 a0 = {0,0,0,0}, a1 = a0, a2 = a0, a3 = a0;
            const float* xp = sX + c*2560 + dg*4;
            const float* ap = At + ng*4;
            #pragma unroll 5
            for (int m = 0; m < NF; ++m) {
                float4 xv = *(const float4*)(xp + m*64);
                float4 av = *(const float4*)(ap + m*NF);
                a0.x += av.x*xv.x; a0.y += av.x*xv.y; a0.z += av.x*xv.z; a0.w += av.x*xv.w;
                a1.x += av.y*xv.x; a1.y += av.y*xv.y; a1.z += av.y*xv.z; a1.w += av.y*xv.w;
                a2.x += av.z*xv.x; a2.y += av.z*xv.y; a2.z += av.z*xv.z; a2.w += av.z*xv.w;
                a3.x += av.w*xv.x; a3.y += av.w*xv.y; a3.z += av.w*xv.z; a3.w += av.w*xv.w;
            }
            float4 accs[4] = {a0, a1, a2, a3};
            #pragma unroll
            for (int k = 0; k < 4; ++k) {
                int n = ng*4 + k;
                float4 sv = __ldg((const float4*)(St + n*128 + 64 + dg*4));
                float4 o = accs[k];
                o.x *= sv.x; o.y *= sv.y; o.z *= sv.z; o.w *= sv.w;
                *(float4*)(sCat + (c*40 + n)*CSTR + 64 + dg*4) = o;
            }
        }
        __syncthreads();

        // ---- phase B: GEMM  sCat[160x128] @ W_t[128x64] -> g_H + bias ----
        const float* Bt = sW + t*8192 + cg*8;
        float acc[5][8];
        #pragma unroll
        for (int i = 0; i < 5; ++i)
            #pragma unroll
            for (int j = 0; j < 8; ++j) acc[i][j] = 0.f;

        const float* Ab = sCat + (rg*5)*CSTR;
        #pragma unroll 2
        for (int f0 = 0; f0 < 128; f0 += 4) {
            float a_[5][4];
            #pragma unroll
            for (int i = 0; i < 5; ++i) {
                float4 av = *(const float4*)(Ab + i*CSTR + f0);
                a_[i][0] = av.x; a_[i][1] = av.y; a_[i][2] = av.z; a_[i][3] = av.w;
            }
            #pragma unroll
            for (int ff = 0; ff < 4; ++ff) {
                float4 b0 = *(const float4*)(Bt + (f0+ff)*64);
                float4 b1 = *(const float4*)(Bt + (f0+ff)*64 + 4);
                #pragma unroll
                for (int i = 0; i < 5; ++i) {
                    float av = a_[i][ff];
                    acc[i][0] += av*b0.x; acc[i][1] += av*b0.y;
                    acc[i][2] += av*b0.z; acc[i][3] += av*b0.w;
                    acc[i][4] += av*b1.x; acc[i][5] += av*b1.y;
                    acc[i][6] += av*b1.z; acc[i][7] += av*b1.w;
                }
            }
        }

        // ---- epilogue: + bias, store to g_H ----
        #pragma unroll
        for (int i = 0; i < 5; ++i) {
            int row = rg*5 + i;
            int c = row / 40;
            int n = row - c*40;
            int b = b0 + c;
            float4 bp0 = __ldg((const float4*)(g_BP + t*2560 + n*64 + cg*8));
            float4 bp1 = __ldg((const float4*)(g_BP + t*2560 + n*64 + cg*8 + 4));
            float* hp = g_H + ((((size_t)b*TT + t)*NF + n) * DD) + cg*8;
            float4 o0 = make_float4(acc[i][0]+bp0.x, acc[i][1]+bp0.y,
                                    acc[i][2]+bp0.z, acc[i][3]+bp0.w);
            float4 o1 = make_float4(acc[i][4]+bp1.x, acc[i][5]+bp1.y,
                                    acc[i][6]+bp1.z, acc[i][7]+bp1.w);
            *(float4*)hp = o0;
            *(float4*)(hp + 4) = o1;
        }
        __syncthreads();   // sCat reused next t
    }
}

// ---------------- kernel 2: gate GEMM + softmax + pooled output ----------
// M = 16384 rows (b,t), K = 2560, N = 40. M-tile 64 -> grid 256, 128 thr.
// 4 rows x 5 cols per thread, float4 K, double-buffered smem tiles.
#define GT_TM 64
#define GSTR  68
#define GH_SZ (GT_TM*GSTR)   // 4352
#define GG_SZ (NF*GSTR)      // 2720
#define GDYN_FLOATS (2*GH_SZ + 2*GG_SZ)  // 14144 floats
__global__ __launch_bounds__(128)
void k_gate(const float* __restrict__ gate_b, float* __restrict__ out) {
    extern __shared__ float gsm[];
    // layout: sH0 @0, sH1 @GH_SZ, sG0 @2*GH_SZ, sG1 @2*GH_SZ+GG_SZ
    int tid  = threadIdx.x;
    int row0 = blockIdx.x * GT_TM;
    int rg = tid >> 3;   // 0..15 -> 4 rows each
    int cg = tid & 7;    // 0..7  -> 5 cols each

    float acc[4][5];
    #pragma unroll
    for (int i = 0; i < 4; ++i)
        #pragma unroll
        for (int j = 0; j < 5; ++j) acc[i][j] = 0.f;

    // preload chunk 0 into buffer 0
    {
        float* sH = gsm;
        float* sG = gsm + 2*GH_SZ;
        #pragma unroll
        for (int q = 0; q < 8; ++q) {
            int idx = tid + q*128;
            int r = idx >> 4, kq = idx & 15;
            *(float4*)(sH + r*GSTR + kq*4) =
                *(const float4*)(g_H + (size_t)(row0 + r)*2560 + kq*4);
        }
        #pragma unroll
        for (int q = 0; q < 5; ++q) {
            int idx = tid + q*128;
            if (idx < 640) {
                int c = idx >> 4, kq = idx & 15;
                *(float4*)(sG + c*GSTR + kq*4) =
                    *(const float4*)(g_GT + (size_t)c*2560 + kq*4);
            }
        }
    }
    __syncthreads();

    for (int ck = 0; ck < 40; ++ck) {
        int cur = ck & 1;
        float* sH = gsm + cur*GH_SZ;
        float* sG = gsm + 2*GH_SZ + cur*GG_SZ;
        float* nH = gsm + (cur^1)*GH_SZ;
        float* nG = gsm + 2*GH_SZ + (cur^1)*GG_SZ;

        float4 hreg[8], greg[5];
        bool more = (ck + 1) < 40;
        if (more) {
            int k0n = (ck + 1) * 64;
            #pragma unroll
            for (int q = 0; q < 8; ++q) {
                int idx = tid + q*128;
                int r = idx >> 4, kq = idx & 15;
                hreg[q] = *(const float4*)(g_H + (size_t)(row0 + r)*2560 + k0n + kq*4);
            }
            #pragma unroll
            for (int q = 0; q < 5; ++q) {
                int idx = tid + q*128;
                if (idx < 640) {
                    int c = idx >> 4, kq = idx & 15;
                    greg[q] = *(const float4*)(g_GT + (size_t)c*2560 + k0n + kq*4);
                }
            }
        }

        #pragma unroll
        for (int k4 = 0; k4 < 16; ++k4) {
            float4 hv[4], gv[5];
            #pragma unroll
            for (int i = 0; i < 4; ++i)
                hv[i] = *(const float4*)(sH + (rg*4 + i)*GSTR + k4*4);
            #pragma unroll
            for (int j = 0; j < 5; ++j)
                gv[j] = *(const float4*)(sG + (cg*5 + j)*GSTR + k4*4);
            #pragma unroll
            for (int i = 0; i < 4; ++i)
                #pragma unroll
                for (int j = 0; j < 5; ++j) {
                    acc[i][j] += hv[i].x * gv[j].x;
                    acc[i][j] += hv[i].y * gv[j].y;
                    acc[i][j] += hv[i].z * gv[j].z;
                    acc[i][j] += hv[i].w * gv[j].w;
                }
        }

        if (more) {
            #pragma unroll
            for (int q = 0; q < 8; ++q) {
                int idx = tid + q*128;
                int r = idx >> 4, kq = idx & 15;
                *(float4*)(nH + r*GSTR + kq*4) = hreg[q];
            }
            #pragma unroll
            for (int q = 0; q < 5; ++q) {
                int idx = tid + q*128;
                if (idx < 640) {
                    int c = idx >> 4, kq = idx & 15;
                    *(float4*)(nG + c*GSTR + kq*4) = greg[q];
                }
            }
        }
        __syncthreads();
    }

    // logits -> smem (reuse gsm as [64][41])
    #pragma unroll
    for (int i = 0; i < 4; ++i)
        #pragma unroll
        for (int j = 0; j < 5; ++j)
            gsm[(rg*4 + i)*41 + cg*5 + j] = acc[i][j] + __ldg(gate_b + cg*5 + j);
    __syncthreads();

    // per-row softmax in place
    if (tid < GT_TM) {
        float* lp = gsm + tid*41;
        float mx = -1e30f;
        #pragma unroll 8
        for (int n = 0; n < NF; ++n) mx = fmaxf(mx, lp[n]);
        float se = 0.f;
        #pragma unroll 8
        for (int n = 0; n < NF; ++n) se += expf(lp[n] - mx);
        float inv = 1.f / se;
        #pragma unroll 8
        for (int n = 0; n < NF; ++n) lp[n] = expf(lp[n] - mx) * inv;
    }
    __syncthreads();

    // pool: out[row, d] = sum_n w[row,n] * h[row, n*64+d]
    {
        int row = tid >> 1;
        int off = (tid & 1) * 32;
        const float* hp = g_H + (size_t)(row0 + row)*2560 + off;
        const float* wp = gsm + row*41;
        float4 a[8];
        #pragma unroll
        for (int q = 0; q < 8; ++q) a[q] = make_float4(0.f, 0.f, 0.f, 0.f);
        #pragma unroll 4
        for (int n = 0; n < NF; ++n) {
            float wv = wp[n];
            const float4* h4 = (const float4*)(hp + n*64);
            #pragma unroll
            for (int q = 0; q < 8; ++q) {
                float4 hv = h4[q];
                a[q].x += wv * hv.x;
                a[q].y += wv * hv.y;
                a[q].z += wv * hv.z;
                a[q].w += wv * hv.w;
            }
        }
        float* op = out + (size_t)(row0 + row)*64 + off;
        #pragma unroll
        for (int q = 0; q < 8; ++q) *(float4*)(op + q*4) = a[q];
    }
}

// ---------------- launcher ------------------------------------------------
extern "C" void kernel_launch(void* const* d_in, const int* in_sizes, int n_in,
                              void* d_out, int out_size) {
    const float* x        = (const float*)d_in[0];
    const float* masker   = (const float*)d_in[1];
    const float* ln_gamma = (const float*)d_in[2];
    const float* ln_beta  = (const float*)d_in[3];
    const float* gnn_w    = (const float*)d_in[4];
    const float* gnn_b    = (const float*)d_in[5];
    const float* bn_gamma = (const float*)d_in[6];
    const float* bn_beta  = (const float*)d_in[7];
    const float* bn_mean  = (const float*)d_in[8];
    const float* bn_var   = (const float*)d_in[9];
    const float* gate_w   = (const float*)d_in[10];
    const float* gate_b   = (const float*)d_in[11];
    float* out = (float*)d_out;

    cudaFuncSetAttribute(k_forward, cudaFuncAttributeMaxDynamicSharedMemorySize,
                         SMEM1_FLOATS * (int)sizeof(float));
    cudaFuncSetAttribute(k_gate, cudaFuncAttributeMaxDynamicSharedMemorySize,
                         GDYN_FLOATS * (int)sizeof(float));

    prep_adj<<<2, 256>>>(masker, ln_gamma, ln_beta);
    prep_sbp<<<80, 128>>>(bn_gamma, bn_beta, bn_mean, bn_var, gnn_w, gnn_b);
    prep_gt<<<(NF*2560 + 255)/256, 256>>>(gate_w);
    k_forward<<<BSZ / CHUNK, 256, SMEM1_FLOATS * sizeof(float)>>>(x, gnn_w);
    k_gate<<<BSZ * TT / GT_TM, 128, GDYN_FLOATS * sizeof(float)>>>(gate_b, out);
}

// round 5
// speedup vs baseline: 1.4534x; 1.0322x over previous
#include <cuda_runtime.h>
#include <math.h>
#include <stdint.h>

#define BSZ   8192
#define TT    2
#define NF    40
#define DD    64
#define FEPS  1e-5f
#define CHUNK 4

typedef unsigned long long u64;

// ---- packed f32x2 helpers (sm_100+): two exact fp32 ops per instruction ----
__device__ __forceinline__ void ffma2(u64& d, u64 a, u64 b) {
    asm("fma.rn.f32x2 %0, %1, %2, %0;" : "+l"(d) : "l"(a), "l"(b));
}
__device__ __forceinline__ u64 mul2(u64 a, u64 b) {
    u64 r; asm("mul.rn.f32x2 %0, %1, %2;" : "=l"(r) : "l"(a), "l"(b)); return r;
}
__device__ __forceinline__ u64 bcast2(float v) {
    u64 r; asm("mov.b64 %0, {%1, %1};" : "=l"(r) : "f"(v)); return r;
}
__device__ __forceinline__ float2 unpk(u64 v) {
    float2 r; asm("mov.b64 {%0, %1}, %2;" : "=f"(r.x), "=f"(r.y) : "l"(v)); return r;
}

// ---------------- device scratch (no allocations allowed) ----------------
__device__ float g_A [TT*NF*NF];          // attention matrices  (t,m,n)
__device__ float g_S [TT*NF*128];         // BN scale per (t,n,f)
__device__ float g_BP[TT*NF*DD];          // folded bias per (t,n,d)
__device__ float g_H [(size_t)BSZ*TT*NF*DD]; // h scratch (b,t,n,d)  168MB
__device__ float g_GT[NF*NF*DD];          // gate_w transposed: [n'][k] 40x2560

// ---------------- prep 1: adjacency -> LN -> mask -> softmax -> A --------
__global__ void prep_adj(const float* __restrict__ masker,
                         const float* __restrict__ ln_gamma,
                         const float* __restrict__ ln_beta) {
    int t = blockIdx.x;
    __shared__ float sadj[NF*NF];
    int tid = threadIdx.x;
    const float* mk = masker + (size_t)t * 3 * NF * NF;
    for (int i = tid; i < NF*NF; i += blockDim.x) {
        float p = mk[i] * mk[NF*NF + i] * mk[2*NF*NF + i];
        sadj[i] = p > 0.f ? p : 0.f;
    }
    __syncthreads();
    if (tid < NF) {
        int j = tid;
        float sum = 0.f, sq = 0.f;
        for (int i = 0; i < NF; ++i) { float a = sadj[i*NF + j]; sum += a; sq += a*a; }
        float mu  = sum * (1.f/NF);
        float var = sq * (1.f/NF) - mu*mu;
        float rs  = rsqrtf(var + FEPS);
        float xm[NF];
        float mx = -1e30f;
        for (int i = 0; i < NF; ++i) {
            float a   = sadj[i*NF + j];
            float msk = (a != 0.f) ? 1.f : 0.f;
            float v   = (a - mu) * rs * ln_gamma[i] + ln_beta[i];
            v += (1.f - msk) * (-1e9f);
            if (i == j) v += 1.f;
            xm[i] = v;
            mx = fmaxf(mx, v);
        }
        float se = 0.f;
        for (int i = 0; i < NF; ++i) { xm[i] = expf(xm[i] - mx); se += xm[i]; }
        float inv = 1.f / se;
        for (int i = 0; i < NF; ++i) {
            float a   = sadj[i*NF + j];
            float msk = (a != 0.f) ? 1.f : 0.f;
            g_A[t*NF*NF + i*NF + j] = xm[i] * inv * msk;
        }
    }
}

// ---------------- prep 2: fold BN into scale s and bias b' ---------------
__global__ void prep_sbp(const float* __restrict__ bn_gamma,
                         const float* __restrict__ bn_beta,
                         const float* __restrict__ bn_mean,
                         const float* __restrict__ bn_var,
                         const float* __restrict__ gnn_w,
                         const float* __restrict__ gnn_b) {
    int blk = blockIdx.x;          // t*40 + n
    int t = blk / NF, n = blk - t*NF;
    __shared__ float so[128];
    int tid = threadIdx.x;         // 128 threads
    int F = blk*128 + tid;
    float s = bn_gamma[F] * rsqrtf(bn_var[F] + FEPS);
    float o = bn_beta[F] - bn_mean[F] * s;
    g_S[blk*128 + tid] = s;
    so[tid] = o;
    __syncthreads();
    if (tid < DD) {
        float acc = gnn_b[t*NF*DD + n*DD + tid];
        #pragma unroll 8
        for (int f = 0; f < 128; ++f)
            acc += so[f] * gnn_w[t*128*DD + f*DD + tid];
        g_BP[blk*DD + tid] = acc;
    }
}

// ---------------- prep 3: transpose gate_w -> g_GT [n'][k] --------------
__global__ void prep_gt(const float* __restrict__ gate_w) {
    int i = blockIdx.x * 256 + threadIdx.x;  // i = c*2560 + k
    if (i < NF * 2560) {
        int c = i / 2560;
        int k = i - c * 2560;
        g_GT[i] = gate_w[k * NF + c];
    }
}

// ---------------- kernel 1: nei + scaled GNN transform -> h --------------
// smem (floats):
//  sA   [2][40][40]      @ 0       (3200)
//  sW   [2][128][64]     @ 3200    (16384)
//  sX   [4][40][64]      @ 19584   (10240)
//  sCat [160][132]       @ 29824   (21120)   (stride 132 = conflict-free)
// total 50944 floats = 203776 B
#define SMEM1_FLOATS 50944
#define CSTR 132
__global__ __launch_bounds__(256, 1)
void k_forward(const float* __restrict__ x, const float* __restrict__ gnn_w) {
    extern __shared__ float sm[];
    float* sA   = sm;
    float* sW   = sm + 3200;
    float* sX   = sm + 19584;
    float* sCat = sm + 29824;

    int tid  = threadIdx.x;
    int b0   = blockIdx.x * CHUNK;

    for (int i = tid; i < 3200;  i += 256) sA[i] = g_A[i];
    for (int i = tid; i < 16384; i += 256) sW[i] = gnn_w[i];
    const float* xb = x + (size_t)b0 * NF * DD;
    for (int i = tid; i < 10240; i += 256) sX[i] = xb[i];
    __syncthreads();

    int rg = tid >> 3;    // 0..31 -> 5 rows each
    int cg = tid & 7;     // 0..7  -> 8 cols each

    for (int t = 0; t < TT; ++t) {
        const float* St = g_S + t * NF * 128;

        // ---- lower half of sCat: x * s_lo  (packed) ----
        for (int i = tid; i < 2560; i += 256) {      // i indexes float4
            int row = i >> 4;                         // 16 float4 per row
            int dq  = (i & 15) * 4;
            int n   = row - (row / 40) * 40;
            ulonglong2 xv = *(const ulonglong2*)(sX + row*64 + dq);
            ulonglong2 sv = *(const ulonglong2*)(St + n*128 + dq);
            ulonglong2 ov;
            ov.x = mul2(xv.x, sv.x);
            ov.y = mul2(xv.y, sv.y);
            *(ulonglong2*)(sCat + row*CSTR + dq) = ov;
        }

        // ---- upper half: nei * s_hi  (phase A, packed over d) ----
        const float* At = sA + t * NF * NF;
        for (int tile = tid; tile < 640; tile += 256) {
            int c  = tile / 160;
            int r  = tile - c * 160;
            int ng = r >> 4;     // n-group of 4
            int dg = r & 15;     // d-group of 4
            u64 acc2[4][2];
            #pragma unroll
            for (int k = 0; k < 4; ++k) { acc2[k][0] = 0ull; acc2[k][1] = 0ull; }
            const float* xp = sX + c*2560 + dg*4;
            const float* ap = At + ng*4;
            #pragma unroll 5
            for (int m = 0; m < NF; ++m) {
                ulonglong2 xv = *(const ulonglong2*)(xp + m*64);
                float4 av = *(const float4*)(ap + m*NF);
                u64 a0 = bcast2(av.x), a1 = bcast2(av.y);
                u64 a2 = bcast2(av.z), a3 = bcast2(av.w);
                ffma2(acc2[0][0], a0, xv.x); ffma2(acc2[0][1], a0, xv.y);
                ffma2(acc2[1][0], a1, xv.x); ffma2(acc2[1][1], a1, xv.y);
                ffma2(acc2[2][0], a2, xv.x); ffma2(acc2[2][1], a2, xv.y);
                ffma2(acc2[3][0], a3, xv.x); ffma2(acc2[3][1], a3, xv.y);
            }
            #pragma unroll
            for (int k = 0; k < 4; ++k) {
                int n = ng*4 + k;
                ulonglong2 sv = *(const ulonglong2*)(St + n*128 + 64 + dg*4);
                ulonglong2 ov;
                ov.x = mul2(acc2[k][0], sv.x);
                ov.y = mul2(acc2[k][1], sv.y);
                *(ulonglong2*)(sCat + (c*40 + n)*CSTR + 64 + dg*4) = ov;
            }
        }
        __syncthreads();

        // ---- phase B: GEMM  sCat[160x128] @ W_t[128x64], packed over d ----
        const float* Bt = sW + t*8192 + cg*8;
        u64 acc[5][4];   // 5 rows x 4 d-pairs (8 cols)
        #pragma unroll
        for (int i = 0; i < 5; ++i)
            #pragma unroll
            for (int j = 0; j < 4; ++j) acc[i][j] = 0ull;

        const float* Ab = sCat + (rg*5)*CSTR;
        #pragma unroll 2
        for (int f0 = 0; f0 < 128; f0 += 4) {
            float a_[5][4];
            #pragma unroll
            for (int i = 0; i < 5; ++i) {
                float4 av = *(const float4*)(Ab + i*CSTR + f0);
                a_[i][0] = av.x; a_[i][1] = av.y; a_[i][2] = av.z; a_[i][3] = av.w;
            }
            #pragma unroll
            for (int ff = 0; ff < 4; ++ff) {
                ulonglong2 b0 = *(const ulonglong2*)(Bt + (f0+ff)*64);
                ulonglong2 b1 = *(const ulonglong2*)(Bt + (f0+ff)*64 + 4);
                #pragma unroll
                for (int i = 0; i < 5; ++i) {
                    u64 ap2 = bcast2(a_[i][ff]);
                    ffma2(acc[i][0], ap2, b0.x);
                    ffma2(acc[i][1], ap2, b0.y);
                    ffma2(acc[i][2], ap2, b1.x);
                    ffma2(acc[i][3], ap2, b1.y);
                }
            }
        }

        // ---- epilogue: + bias, store to g_H ----
        #pragma unroll
        for (int i = 0; i < 5; ++i) {
            int row = rg*5 + i;
            int c = row / 40;
            int n = row - c*40;
            int b = b0 + c;
            float4 bp0 = __ldg((const float4*)(g_BP + t*2560 + n*64 + cg*8));
            float4 bp1 = __ldg((const float4*)(g_BP + t*2560 + n*64 + cg*8 + 4));
            float2 p0 = unpk(acc[i][0]), p1 = unpk(acc[i][1]);
            float2 p2 = unpk(acc[i][2]), p3 = unpk(acc[i][3]);
            float* hp = g_H + ((((size_t)b*TT + t)*NF + n) * DD) + cg*8;
            float4 o0 = make_float4(p0.x+bp0.x, p0.y+bp0.y, p1.x+bp0.z, p1.y+bp0.w);
            float4 o1 = make_float4(p2.x+bp1.x, p2.y+bp1.y, p3.x+bp1.z, p3.y+bp1.w);
            *(float4*)hp = o0;
            *(float4*)(hp + 4) = o1;
        }
        __syncthreads();   // sCat reused next t
    }
}

// ---------------- kernel 2: gate GEMM + softmax + pooled output ----------
// M = 16384 rows (b,t), K = 2560, N = 40. M-tile 64 -> grid 256, 128 thr.
// 4 rows x 5 cols per thread, packed f32x2 over K, double-buffered tiles.
#define GT_TM 64
#define GSTR  68
#define GH_SZ (GT_TM*GSTR)   // 4352
#define GG_SZ (NF*GSTR)      // 2720
#define GDYN_FLOATS (2*GH_SZ + 2*GG_SZ)  // 14144 floats
__global__ __launch_bounds__(128)
void k_gate(const float* __restrict__ gate_b, float* __restrict__ out) {
    extern __shared__ float gsm[];
    // layout: sH0 @0, sH1 @GH_SZ, sG0 @2*GH_SZ, sG1 @2*GH_SZ+GG_SZ
    int tid  = threadIdx.x;
    int row0 = blockIdx.x * GT_TM;
    int rg = tid >> 3;   // 0..15 -> 4 rows each
    int cg = tid & 7;    // 0..7  -> 5 cols each

    u64 acc[4][5];       // packed partial sums over even/odd k
    #pragma unroll
    for (int i = 0; i < 4; ++i)
        #pragma unroll
        for (int j = 0; j < 5; ++j) acc[i][j] = 0ull;

    // preload chunk 0 into buffer 0
    {
        float* sH = gsm;
        float* sG = gsm + 2*GH_SZ;
        #pragma unroll
        for (int q = 0; q < 8; ++q) {
            int idx = tid + q*128;
            int r = idx >> 4, kq = idx & 15;
            *(float4*)(sH + r*GSTR + kq*4) =
                *(const float4*)(g_H + (size_t)(row0 + r)*2560 + kq*4);
        }
        #pragma unroll
        for (int q = 0; q < 5; ++q) {
            int idx = tid + q*128;
            if (idx < 640) {
                int c = idx >> 4, kq = idx & 15;
                *(float4*)(sG + c*GSTR + kq*4) =
                    *(const float4*)(g_GT + (size_t)c*2560 + kq*4);
            }
        }
    }
    __syncthreads();

    for (int ck = 0; ck < 40; ++ck) {
        int cur = ck & 1;
        float* sH = gsm + cur*GH_SZ;
        float* sG = gsm + 2*GH_SZ + cur*GG_SZ;
        float* nH = gsm + (cur^1)*GH_SZ;
        float* nG = gsm + 2*GH_SZ + (cur^1)*GG_SZ;

        float4 hreg[8], greg[5];
        bool more = (ck + 1) < 40;
        if (more) {
            int k0n = (ck + 1) * 64;
            #pragma unroll
            for (int q = 0; q < 8; ++q) {
                int idx = tid + q*128;
                int r = idx >> 4, kq = idx & 15;
                hreg[q] = *(const float4*)(g_H + (size_t)(row0 + r)*2560 + k0n + kq*4);
            }
            #pragma unroll
            for (int q = 0; q < 5; ++q) {
                int idx = tid + q*128;
                if (idx < 640) {
                    int c = idx >> 4, kq = idx & 15;
                    greg[q] = *(const float4*)(g_GT + (size_t)c*2560 + k0n + kq*4);
                }
            }
        }

        #pragma unroll
        for (int k4 = 0; k4 < 16; ++k4) {
            ulonglong2 hv[4], gv[5];
            #pragma unroll
            for (int i = 0; i < 4; ++i)
                hv[i] = *(const ulonglong2*)(sH + (rg*4 + i)*GSTR + k4*4);
            #pragma unroll
            for (int j = 0; j < 5; ++j)
                gv[j] = *(const ulonglong2*)(sG + (cg*5 + j)*GSTR + k4*4);
            #pragma unroll
            for (int i = 0; i < 4; ++i)
                #pragma unroll
                for (int j = 0; j < 5; ++j) {
                    ffma2(acc[i][j], hv[i].x, gv[j].x);
                    ffma2(acc[i][j], hv[i].y, gv[j].y);
                }
        }

        if (more) {
            #pragma unroll
            for (int q = 0; q < 8; ++q) {
                int idx = tid + q*128;
                int r = idx >> 4, kq = idx & 15;
                *(float4*)(nH + r*GSTR + kq*4) = hreg[q];
            }
            #pragma unroll
            for (int q = 0; q < 5; ++q) {
                int idx = tid + q*128;
                if (idx < 640) {
                    int c = idx >> 4, kq = idx & 15;
                    *(float4*)(nG + c*GSTR + kq*4) = greg[q];
                }
            }
        }
        __syncthreads();
    }

    // logits -> smem (reuse gsm as [64][41]); horizontal add of k-packs
    #pragma unroll
    for (int i = 0; i < 4; ++i)
        #pragma unroll
        for (int j = 0; j < 5; ++j) {
            float2 p = unpk(acc[i][j]);
            gsm[(rg*4 + i)*41 + cg*5 + j] = p.x + p.y + __ldg(gate_b + cg*5 + j);
        }
    __syncthreads();

    // per-row softmax in place
    if (tid < GT_TM) {
        float* lp = gsm + tid*41;
        float mx = -1e30f;
        #pragma unroll 8
        for (int n = 0; n < NF; ++n) mx = fmaxf(mx, lp[n]);
        float se = 0.f;
        #pragma unroll 8
        for (int n = 0; n < NF; ++n) se += expf(lp[n] - mx);
        float inv = 1.f / se;
        #pragma unroll 8
        for (int n = 0; n < NF; ++n) lp[n] = expf(lp[n] - mx) * inv;
    }
    __syncthreads();

    // pool: out[row, d] = sum_n w[row,n] * h[row, n*64+d]
    {
        int row = tid >> 1;
        int off = (tid & 1) * 32;
        const float* hp = g_H + (size_t)(row0 + row)*2560 + off;
        const float* wp = gsm + row*41;
        float4 a[8];
        #pragma unroll
        for (int q = 0; q < 8; ++q) a[q] = make_float4(0.f, 0.f, 0.f, 0.f);
        #pragma unroll 4
        for (int n = 0; n < NF; ++n) {
            float wv = wp[n];
            const float4* h4 = (const float4*)(hp + n*64);
            #pragma unroll
            for (int q = 0; q < 8; ++q) {
                float4 hv = h4[q];
                a[q].x += wv * hv.x;
                a[q].y += wv * hv.y;
                a[q].z += wv * hv.z;
                a[q].w += wv * hv.w;
            }
        }
        float* op = out + (size_t)(row0 + row)*64 + off;
        #pragma unroll
        for (int q = 0; q < 8; ++q) *(float4*)(op + q*4) = a[q];
    }
}

// ---------------- launcher ------------------------------------------------
extern "C" void kernel_launch(void* const* d_in, const int* in_sizes, int n_in,
                              void* d_out, int out_size) {
    const float* x        = (const float*)d_in[0];
    const float* masker   = (const float*)d_in[1];
    const float* ln_gamma = (const float*)d_in[2];
    const float* ln_beta  = (const float*)d_in[3];
    const float* gnn_w    = (const float*)d_in[4];
    const float* gnn_b    = (const float*)d_in[5];
    const float* bn_gamma = (const float*)d_in[6];
    const float* bn_beta  = (const float*)d_in[7];
    const float* bn_mean  = (const float*)d_in[8];
    const float* bn_var   = (const float*)d_in[9];
    const float* gate_w   = (const float*)d_in[10];
    const float* gate_b   = (const float*)d_in[11];
    float* out = (float*)d_out;

    cudaFuncSetAttribute(k_forward, cudaFuncAttributeMaxDynamicSharedMemorySize,
                         SMEM1_FLOATS * (int)sizeof(float));
    cudaFuncSetAttribute(k_gate, cudaFuncAttributeMaxDynamicSharedMemorySize,
                         GDYN_FLOATS * (int)sizeof(float));

    prep_adj<<<2, 256>>>(masker, ln_gamma, ln_beta);
    prep_sbp<<<80, 128>>>(bn_gamma, bn_beta, bn_mean, bn_var, gnn_w, gnn_b);
    prep_gt<<<(NF*2560 + 255)/256, 256>>>(gate_w);
    k_forward<<<BSZ / CHUNK, 256, SMEM1_FLOATS * sizeof(float)>>>(x, gnn_w);
    k_gate<<<BSZ * TT / GT_TM, 128, GDYN_FLOATS * sizeof(float)>>>(gate_b, out);
}

// round 6
// speedup vs baseline: 1.8033x; 1.2408x over previous
#include <cuda_runtime.h>
#include <math.h>
#include <stdint.h>

#define BSZ   8192
#define TT    2
#define NF    40
#define DD    64
#define FEPS  1e-5f
#define CHUNK 2

typedef unsigned long long u64;

// ---- packed f32x2 helpers (sm_100+): two exact fp32 ops per instruction ----
__device__ __forceinline__ void ffma2(u64& d, u64 a, u64 b) {
    asm("fma.rn.f32x2 %0, %1, %2, %0;" : "+l"(d) : "l"(a), "l"(b));
}
__device__ __forceinline__ u64 mul2(u64 a, u64 b) {
    u64 r; asm("mul.rn.f32x2 %0, %1, %2;" : "=l"(r) : "l"(a), "l"(b)); return r;
}
__device__ __forceinline__ u64 bcast2(float v) {
    u64 r; asm("mov.b64 %0, {%1, %1};" : "=l"(r) : "f"(v)); return r;
}
__device__ __forceinline__ float2 unpk(u64 v) {
    float2 r; asm("mov.b64 {%0, %1}, %2;" : "=f"(r.x), "=f"(r.y) : "l"(v)); return r;
}

// ---------------- device scratch (no allocations allowed) ----------------
__device__ float g_A [TT*NF*NF];          // attention matrices  (t,m,n)
__device__ float g_S [TT*NF*128];         // BN scale per (t,n,f)
__device__ float g_BP[TT*NF*DD];          // folded bias per (t,n,d)
__device__ float g_H [(size_t)BSZ*TT*NF*DD]; // h scratch (b,t,n,d)  168MB
__device__ float g_GT[NF*NF*DD];          // gate_w transposed: [n'][k] 40x2560

// ---------------- prep 1: adjacency -> LN -> mask -> softmax -> A --------
__global__ void prep_adj(const float* __restrict__ masker,
                         const float* __restrict__ ln_gamma,
                         const float* __restrict__ ln_beta) {
    int t = blockIdx.x;
    __shared__ float sadj[NF*NF];
    int tid = threadIdx.x;
    const float* mk = masker + (size_t)t * 3 * NF * NF;
    for (int i = tid; i < NF*NF; i += blockDim.x) {
        float p = mk[i] * mk[NF*NF + i] * mk[2*NF*NF + i];
        sadj[i] = p > 0.f ? p : 0.f;
    }
    __syncthreads();
    if (tid < NF) {
        int j = tid;
        float sum = 0.f, sq = 0.f;
        for (int i = 0; i < NF; ++i) { float a = sadj[i*NF + j]; sum += a; sq += a*a; }
        float mu  = sum * (1.f/NF);
        float var = sq * (1.f/NF) - mu*mu;
        float rs  = rsqrtf(var + FEPS);
        float xm[NF];
        float mx = -1e30f;
        for (int i = 0; i < NF; ++i) {
            float a   = sadj[i*NF + j];
            float msk = (a != 0.f) ? 1.f : 0.f;
            float v   = (a - mu) * rs * ln_gamma[i] + ln_beta[i];
            v += (1.f - msk) * (-1e9f);
            if (i == j) v += 1.f;
            xm[i] = v;
            mx = fmaxf(mx, v);
        }
        float se = 0.f;
        for (int i = 0; i < NF; ++i) { xm[i] = expf(xm[i] - mx); se += xm[i]; }
        float inv = 1.f / se;
        for (int i = 0; i < NF; ++i) {
            float a   = sadj[i*NF + j];
            float msk = (a != 0.f) ? 1.f : 0.f;
            g_A[t*NF*NF + i*NF + j] = xm[i] * inv * msk;
        }
    }
}

// ---------------- prep 2: fold BN into scale s and bias b' ---------------
__global__ void prep_sbp(const float* __restrict__ bn_gamma,
                         const float* __restrict__ bn_beta,
                         const float* __restrict__ bn_mean,
                         const float* __restrict__ bn_var,
                         const float* __restrict__ gnn_w,
                         const float* __restrict__ gnn_b) {
    int blk = blockIdx.x;          // t*40 + n
    int t = blk / NF, n = blk - t*NF;
    __shared__ float so[128];
    int tid = threadIdx.x;         // 128 threads
    int F = blk*128 + tid;
    float s = bn_gamma[F] * rsqrtf(bn_var[F] + FEPS);
    float o = bn_beta[F] - bn_mean[F] * s;
    g_S[blk*128 + tid] = s;
    so[tid] = o;
    __syncthreads();
    if (tid < DD) {
        float acc = gnn_b[t*NF*DD + n*DD + tid];
        #pragma unroll 8
        for (int f = 0; f < 128; ++f)
            acc += so[f] * gnn_w[t*128*DD + f*DD + tid];
        g_BP[blk*DD + tid] = acc;
    }
}

// ---------------- prep 3: transpose gate_w -> g_GT [n'][k] --------------
__global__ void prep_gt(const float* __restrict__ gate_w) {
    int i = blockIdx.x * 256 + threadIdx.x;  // i = c*2560 + k
    if (i < NF * 2560) {
        int c = i / 2560;
        int k = i - c * 2560;
        g_GT[i] = gate_w[k * NF + c];
    }
}

// ---------------- kernel 1: nei + scaled GNN transform -> h --------------
// smem (floats), CHUNK=2, per-t weight buffer => 2 CTAs/SM:
//  sA   [2][40][40]      @ 0       (3200)
//  sW   [128][64]        @ 3200    (8192)   current tower only
//  sX   [2][40][64]      @ 11392   (5120)
//  sCat [80][132]        @ 16512   (10560)  (stride 132 conflict-free)
// total 27072 floats = 108288 B  -> 2 CTAs x 108KB = 216KB <= 228KB
#define SMEM1_FLOATS 27072
#define CSTR 132
__global__ __launch_bounds__(256, 2)
void k_forward(const float* __restrict__ x, const float* __restrict__ gnn_w) {
    extern __shared__ float sm[];
    float* sA   = sm;
    float* sW   = sm + 3200;
    float* sX   = sm + 11392;
    float* sCat = sm + 16512;

    int tid  = threadIdx.x;
    int b0   = blockIdx.x * CHUNK;

    for (int i = tid; i < 3200;  i += 256) sA[i] = g_A[i];
    const float* xb = x + (size_t)b0 * NF * DD;
    for (int i = tid; i < 5120; i += 256) sX[i] = xb[i];
    __syncthreads();

    int rg = tid >> 4;    // 0..15 -> 5 rows each   (80 rows)
    int cg = tid & 15;    // 0..15 -> 4 cols each   (64 cols)

    for (int t = 0; t < TT; ++t) {
        const float* St = g_S + t * NF * 128;

        // ---- load this tower's weights (L2-hot, 32KB) ----
        for (int i = tid; i < 2048; i += 256)
            *(float4*)(sW + i*4) = __ldg((const float4*)(gnn_w + t*8192 + i*4));

        // ---- lower half of sCat: x * s_lo  (packed) ----
        for (int i = tid; i < 1280; i += 256) {      // i indexes float4
            int row = i >> 4;                         // 16 float4 per row
            int dq  = (i & 15) * 4;
            int n   = row - (row / 40) * 40;
            ulonglong2 xv = *(const ulonglong2*)(sX + row*64 + dq);
            ulonglong2 sv = *(const ulonglong2*)(St + n*128 + dq);
            ulonglong2 ov;
            ov.x = mul2(xv.x, sv.x);
            ov.y = mul2(xv.y, sv.y);
            *(ulonglong2*)(sCat + row*CSTR + dq) = ov;
        }

        // ---- upper half: nei * s_hi  (phase A, packed over d) ----
        const float* At = sA + t * NF * NF;
        for (int tile = tid; tile < 320; tile += 256) {
            int c  = tile / 160;
            int r  = tile - c * 160;
            int ng = r >> 4;     // n-group of 4
            int dg = r & 15;     // d-group of 4
            u64 acc2[4][2];
            #pragma unroll
            for (int k = 0; k < 4; ++k) { acc2[k][0] = 0ull; acc2[k][1] = 0ull; }
            const float* xp = sX + c*2560 + dg*4;
            const float* ap = At + ng*4;
            #pragma unroll 5
            for (int m = 0; m < NF; ++m) {
                ulonglong2 xv = *(const ulonglong2*)(xp + m*64);
                float4 av = *(const float4*)(ap + m*NF);
                u64 a0 = bcast2(av.x), a1 = bcast2(av.y);
                u64 a2 = bcast2(av.z), a3 = bcast2(av.w);
                ffma2(acc2[0][0], a0, xv.x); ffma2(acc2[0][1], a0, xv.y);
                ffma2(acc2[1][0], a1, xv.x); ffma2(acc2[1][1], a1, xv.y);
                ffma2(acc2[2][0], a2, xv.x); ffma2(acc2[2][1], a2, xv.y);
                ffma2(acc2[3][0], a3, xv.x); ffma2(acc2[3][1], a3, xv.y);
            }
            #pragma unroll
            for (int k = 0; k < 4; ++k) {
                int n = ng*4 + k;
                ulonglong2 sv = *(const ulonglong2*)(St + n*128 + 64 + dg*4);
                ulonglong2 ov;
                ov.x = mul2(acc2[k][0], sv.x);
                ov.y = mul2(acc2[k][1], sv.y);
                *(ulonglong2*)(sCat + (c*40 + n)*CSTR + 64 + dg*4) = ov;
            }
        }
        __syncthreads();

        // ---- phase B: GEMM  sCat[80x128] @ W_t[128x64], packed over d ----
        u64 acc[5][2];   // 5 rows x 2 d-pairs (4 cols)
        #pragma unroll
        for (int i = 0; i < 5; ++i) { acc[i][0] = 0ull; acc[i][1] = 0ull; }

        const float* Ab = sCat + (rg*5)*CSTR;
        const float* Bt = sW + cg*4;
        #pragma unroll 2
        for (int f0 = 0; f0 < 128; f0 += 4) {
            float a_[5][4];
            #pragma unroll
            for (int i = 0; i < 5; ++i) {
                float4 av = *(const float4*)(Ab + i*CSTR + f0);
                a_[i][0] = av.x; a_[i][1] = av.y; a_[i][2] = av.z; a_[i][3] = av.w;
            }
            #pragma unroll
            for (int ff = 0; ff < 4; ++ff) {
                ulonglong2 bv = *(const ulonglong2*)(Bt + (f0+ff)*64);
                #pragma unroll
                for (int i = 0; i < 5; ++i) {
                    u64 ap2 = bcast2(a_[i][ff]);
                    ffma2(acc[i][0], ap2, bv.x);
                    ffma2(acc[i][1], ap2, bv.y);
                }
            }
        }

        // ---- epilogue: + bias, store to g_H ----
        #pragma unroll
        for (int i = 0; i < 5; ++i) {
            int row = rg*5 + i;
            int c = row / 40;
            int n = row - c*40;
            int b = b0 + c;
            float4 bp = __ldg((const float4*)(g_BP + t*2560 + n*64 + cg*4));
            float2 p0 = unpk(acc[i][0]), p1 = unpk(acc[i][1]);
            float* hp = g_H + ((((size_t)b*TT + t)*NF + n) * DD) + cg*4;
            *(float4*)hp = make_float4(p0.x+bp.x, p0.y+bp.y, p1.x+bp.z, p1.y+bp.w);
        }
        __syncthreads();   // sCat & sW reused next t
    }
}

// ---------------- kernel 2: gate GEMM + softmax + pooled output ----------
// M = 16384 rows (b,t), K = 2560, N = 40. M-tile 64 -> grid 256, 128 thr.
// 4 rows x 5 cols per thread, packed f32x2 over K, double-buffered tiles.
#define GT_TM 64
#define GSTR  68
#define GH_SZ (GT_TM*GSTR)   // 4352
#define GG_SZ (NF*GSTR)      // 2720
#define GDYN_FLOATS (2*GH_SZ + 2*GG_SZ)  // 14144 floats
__global__ __launch_bounds__(128)
void k_gate(const float* __restrict__ gate_b, float* __restrict__ out) {
    extern __shared__ float gsm[];
    // layout: sH0 @0, sH1 @GH_SZ, sG0 @2*GH_SZ, sG1 @2*GH_SZ+GG_SZ
    int tid  = threadIdx.x;
    int row0 = blockIdx.x * GT_TM;
    int rg = tid >> 3;   // 0..15 -> 4 rows each
    int cg = tid & 7;    // 0..7  -> 5 cols each

    u64 acc[4][5];       // packed partial sums over even/odd k
    #pragma unroll
    for (int i = 0; i < 4; ++i)
        #pragma unroll
        for (int j = 0; j < 5; ++j) acc[i][j] = 0ull;

    // preload chunk 0 into buffer 0
    {
        float* sH = gsm;
        float* sG = gsm + 2*GH_SZ;
        #pragma unroll
        for (int q = 0; q < 8; ++q) {
            int idx = tid + q*128;
            int r = idx >> 4, kq = idx & 15;
            *(float4*)(sH + r*GSTR + kq*4) =
                *(const float4*)(g_H + (size_t)(row0 + r)*2560 + kq*4);
        }
        #pragma unroll
        for (int q = 0; q < 5; ++q) {
            int idx = tid + q*128;
            if (idx < 640) {
                int c = idx >> 4, kq = idx & 15;
                *(float4*)(sG + c*GSTR + kq*4) =
                    *(const float4*)(g_GT + (size_t)c*2560 + kq*4);
            }
        }
    }
    __syncthreads();

    for (int ck = 0; ck < 40; ++ck) {
        int cur = ck & 1;
        float* sH = gsm + cur*GH_SZ;
        float* sG = gsm + 2*GH_SZ + cur*GG_SZ;
        float* nH = gsm + (cur^1)*GH_SZ;
        float* nG = gsm + 2*GH_SZ + (cur^1)*GG_SZ;

        float4 hreg[8], greg[5];
        bool more = (ck + 1) < 40;
        if (more) {
            int k0n = (ck + 1) * 64;
            #pragma unroll
            for (int q = 0; q < 8; ++q) {
                int idx = tid + q*128;
                int r = idx >> 4, kq = idx & 15;
                hreg[q] = *(const float4*)(g_H + (size_t)(row0 + r)*2560 + k0n + kq*4);
            }
            #pragma unroll
            for (int q = 0; q < 5; ++q) {
                int idx = tid + q*128;
                if (idx < 640) {
                    int c = idx >> 4, kq = idx & 15;
                    greg[q] = *(const float4*)(g_GT + (size_t)c*2560 + k0n + kq*4);
                }
            }
        }

        #pragma unroll
        for (int k4 = 0; k4 < 16; ++k4) {
            ulonglong2 hv[4], gv[5];
            #pragma unroll
            for (int i = 0; i < 4; ++i)
                hv[i] = *(const ulonglong2*)(sH + (rg*4 + i)*GSTR + k4*4);
            #pragma unroll
            for (int j = 0; j < 5; ++j)
                gv[j] = *(const ulonglong2*)(sG + (cg*5 + j)*GSTR + k4*4);
            #pragma unroll
            for (int i = 0; i < 4; ++i)
                #pragma unroll
                for (int j = 0; j < 5; ++j) {
                    ffma2(acc[i][j], hv[i].x, gv[j].x);
                    ffma2(acc[i][j], hv[i].y, gv[j].y);
                }
        }

        if (more) {
            #pragma unroll
            for (int q = 0; q < 8; ++q) {
                int idx = tid + q*128;
                int r = idx >> 4, kq = idx & 15;
                *(float4*)(nH + r*GSTR + kq*4) = hreg[q];
            }
            #pragma unroll
            for (int q = 0; q < 5; ++q) {
                int idx = tid + q*128;
                if (idx < 640) {
                    int c = idx >> 4, kq = idx & 15;
                    *(float4*)(nG + c*GSTR + kq*4) = greg[q];
                }
            }
        }
        __syncthreads();
    }

    // logits -> smem (reuse gsm as [64][41]); horizontal add of k-packs
    #pragma unroll
    for (int i = 0; i < 4; ++i)
        #pragma unroll
        for (int j = 0; j < 5; ++j) {
            float2 p = unpk(acc[i][j]);
            gsm[(rg*4 + i)*41 + cg*5 + j] = p.x + p.y + __ldg(gate_b + cg*5 + j);
        }
    __syncthreads();

    // per-row softmax in place
    if (tid < GT_TM) {
        float* lp = gsm + tid*41;
        float mx = -1e30f;
        #pragma unroll 8
        for (int n = 0; n < NF; ++n) mx = fmaxf(mx, lp[n]);
        float se = 0.f;
        #pragma unroll 8
        for (int n = 0; n < NF; ++n) se += expf(lp[n] - mx);
        float inv = 1.f / se;
        #pragma unroll 8
        for (int n = 0; n < NF; ++n) lp[n] = expf(lp[n] - mx) * inv;
    }
    __syncthreads();

    // pool: out[row, d] = sum_n w[row,n] * h[row, n*64+d]
    {
        int row = tid >> 1;
        int off = (tid & 1) * 32;
        const float* hp = g_H + (size_t)(row0 + row)*2560 + off;
        const float* wp = gsm + row*41;
        float4 a[8];
        #pragma unroll
        for (int q = 0; q < 8; ++q) a[q] = make_float4(0.f, 0.f, 0.f, 0.f);
        #pragma unroll 4
        for (int n = 0; n < NF; ++n) {
            float wv = wp[n];
            const float4* h4 = (const float4*)(hp + n*64);
            #pragma unroll
            for (int q = 0; q < 8; ++q) {
                float4 hv = h4[q];
                a[q].x += wv * hv.x;
                a[q].y += wv * hv.y;
                a[q].z += wv * hv.z;
                a[q].w += wv * hv.w;
            }
        }
        float* op = out + (size_t)(row0 + row)*64 + off;
        #pragma unroll
        for (int q = 0; q < 8; ++q) *(float4*)(op + q*4) = a[q];
    }
}

// ---------------- launcher ------------------------------------------------
extern "C" void kernel_launch(void* const* d_in, const int* in_sizes, int n_in,
                              void* d_out, int out_size) {
    const float* x        = (const float*)d_in[0];
    const float* masker   = (const float*)d_in[1];
    const float* ln_gamma = (const float*)d_in[2];
    const float* ln_beta  = (const float*)d_in[3];
    const float* gnn_w    = (const float*)d_in[4];
    const float* gnn_b    = (const float*)d_in[5];
    const float* bn_gamma = (const float*)d_in[6];
    const float* bn_beta  = (const float*)d_in[7];
    const float* bn_mean  = (const float*)d_in[8];
    const float* bn_var   = (const float*)d_in[9];
    const float* gate_w   = (const float*)d_in[10];
    const float* gate_b   = (const float*)d_in[11];
    float* out = (float*)d_out;

    cudaFuncSetAttribute(k_forward, cudaFuncAttributeMaxDynamicSharedMemorySize,
                         SMEM1_FLOATS * (int)sizeof(float));
    cudaFuncSetAttribute(k_gate, cudaFuncAttributeMaxDynamicSharedMemorySize,
                         GDYN_FLOATS * (int)sizeof(float));

    prep_adj<<<2, 256>>>(masker, ln_gamma, ln_beta);
    prep_sbp<<<80, 128>>>(bn_gamma, bn_beta, bn_mean, bn_var, gnn_w, gnn_b);
    prep_gt<<<(NF*2560 + 255)/256, 256>>>(gate_w);
    k_forward<<<BSZ / CHUNK, 256, SMEM1_FLOATS * sizeof(float)>>>(x, gnn_w);
    k_gate<<<BSZ * TT / GT_TM, 128, GDYN_FLOATS * sizeof(float)>>>(gate_b, out);
}

// round 8
// speedup vs baseline: 1.8746x; 1.0395x over previous
#include <cuda_runtime.h>
#include <cuda_bf16.h>
#include <math.h>
#include <stdint.h>

#define BSZ   8192
#define TT    2
#define NF    40
#define DD    64
#define FEPS  1e-5f
#define CHUNK 2

typedef unsigned long long u64;

// ---- packed f32x2 helpers (exact fp32, 2 ops/instr) ----
__device__ __forceinline__ void ffma2(u64& d, u64 a, u64 b) {
    asm("fma.rn.f32x2 %0, %1, %2, %0;" : "+l"(d) : "l"(a), "l"(b));
}
__device__ __forceinline__ u64 mul2(u64 a, u64 b) {
    u64 r; asm("mul.rn.f32x2 %0, %1, %2;" : "=l"(r) : "l"(a), "l"(b)); return r;
}
__device__ __forceinline__ u64 bcast2(float v) {
    u64 r; asm("mov.b64 %0, {%1, %1};" : "=l"(r) : "f"(v)); return r;
}
__device__ __forceinline__ float2 unpk(u64 v) {
    float2 r; asm("mov.b64 {%0, %1}, %2;" : "=f"(r.x), "=f"(r.y) : "l"(v)); return r;
}

// ---- split-bf16 packing: (a,b) -> hi pair + lo (residual) pair ----
__device__ __forceinline__ void splitpk(float a, float b, uint32_t& hi, uint32_t& lo) {
    __nv_bfloat162 h = __floats2bfloat162_rn(a, b);
    float ra = a - __bfloat162float(h.x);
    float rb = b - __bfloat162float(h.y);
    __nv_bfloat162 l = __floats2bfloat162_rn(ra, rb);
    hi = *reinterpret_cast<uint32_t*>(&h);
    lo = *reinterpret_cast<uint32_t*>(&l);
}

// ---- legacy tensor core mma (sm_80+, allowed on plain sm_103 target) ----
__device__ __forceinline__ void mma_bf16(float* d,
    uint32_t a0, uint32_t a1, uint32_t a2, uint32_t a3,
    uint32_t b0, uint32_t b1) {
    asm volatile(
        "mma.sync.aligned.m16n8k16.row.col.f32.bf16.bf16.f32 "
        "{%0,%1,%2,%3}, {%4,%5,%6,%7}, {%8,%9}, {%0,%1,%2,%3};"
        : "+f"(d[0]), "+f"(d[1]), "+f"(d[2]), "+f"(d[3])
        : "r"(a0), "r"(a1), "r"(a2), "r"(a3), "r"(b0), "r"(b1));
}

// ---------------- device scratch ----------------
__device__ float g_A [TT*NF*NF];
__device__ float g_S [TT*NF*128];
__device__ float g_BP[TT*NF*DD];
__device__ float g_H [(size_t)BSZ*TT*NF*DD];
__device__ float g_GT[NF*NF*DD];
__device__ uint32_t g_WPH[TT*64*64];   // W bf16-hi pairs: [t][f/2][d], low half = even f
__device__ uint32_t g_WPL[TT*64*64];   // W bf16-lo (residual) pairs

// ---------------- prep 1: adjacency -> LN -> mask -> softmax -> A --------
__global__ void prep_adj(const float* __restrict__ masker,
                         const float* __restrict__ ln_gamma,
                         const float* __restrict__ ln_beta) {
    int t = blockIdx.x;
    __shared__ float sadj[NF*NF];
    int tid = threadIdx.x;
    const float* mk = masker + (size_t)t * 3 * NF * NF;
    for (int i = tid; i < NF*NF; i += blockDim.x) {
        float p = mk[i] * mk[NF*NF + i] * mk[2*NF*NF + i];
        sadj[i] = p > 0.f ? p : 0.f;
    }
    __syncthreads();
    if (tid < NF) {
        int j = tid;
        float sum = 0.f, sq = 0.f;
        for (int i = 0; i < NF; ++i) { float a = sadj[i*NF + j]; sum += a; sq += a*a; }
        float mu  = sum * (1.f/NF);
        float var = sq * (1.f/NF) - mu*mu;
        float rs  = rsqrtf(var + FEPS);
        float xm[NF];
        float mx = -1e30f;
        for (int i = 0; i < NF; ++i) {
            float a   = sadj[i*NF + j];
            float msk = (a != 0.f) ? 1.f : 0.f;
            float v   = (a - mu) * rs * ln_gamma[i] + ln_beta[i];
            v += (1.f - msk) * (-1e9f);
            if (i == j) v += 1.f;
            xm[i] = v;
            mx = fmaxf(mx, v);
        }
        float se = 0.f;
        for (int i = 0; i < NF; ++i) { xm[i] = expf(xm[i] - mx); se += xm[i]; }
        float inv = 1.f / se;
        for (int i = 0; i < NF; ++i) {
            float a   = sadj[i*NF + j];
            float msk = (a != 0.f) ? 1.f : 0.f;
            g_A[t*NF*NF + i*NF + j] = xm[i] * inv * msk;
        }
    }
}

// ---------------- prep 2: fold BN into scale s and bias b' ---------------
__global__ void prep_sbp(const float* __restrict__ bn_gamma,
                         const float* __restrict__ bn_beta,
                         const float* __restrict__ bn_mean,
                         const float* __restrict__ bn_var,
                         const float* __restrict__ gnn_w,
                         const float* __restrict__ gnn_b) {
    int blk = blockIdx.x;          // t*40 + n
    int t = blk / NF, n = blk - t*NF;
    __shared__ float so[128];
    int tid = threadIdx.x;
    int F = blk*128 + tid;
    float s = bn_gamma[F] * rsqrtf(bn_var[F] + FEPS);
    float o = bn_beta[F] - bn_mean[F] * s;
    g_S[blk*128 + tid] = s;
    so[tid] = o;
    __syncthreads();
    if (tid < DD) {
        float acc = gnn_b[t*NF*DD + n*DD + tid];
        #pragma unroll 8
        for (int f = 0; f < 128; ++f)
            acc += so[f] * gnn_w[t*128*DD + f*DD + tid];
        g_BP[blk*DD + tid] = acc;
    }
}

// ---------------- prep 3: transpose gate_w ------------------------------
__global__ void prep_gt(const float* __restrict__ gate_w) {
    int i = blockIdx.x * 256 + threadIdx.x;
    if (i < NF * 2560) {
        int c = i / 2560;
        int k = i - c * 2560;
        g_GT[i] = gate_w[k * NF + c];
    }
}

// ---------------- prep 4: W -> split-bf16 pair layout --------------------
__global__ void prep_wp(const float* __restrict__ gnn_w) {
    int i = blockIdx.x * 256 + threadIdx.x;   // t*4096 + p*64 + d
    if (i < TT*64*64) {
        int t = i >> 12, r = i & 4095;
        int p = r >> 6, d = r & 63;
        float w0 = gnn_w[t*8192 + (2*p)*64 + d];
        float w1 = gnn_w[t*8192 + (2*p+1)*64 + d];
        uint32_t hi, lo;
        splitpk(w0, w1, hi, lo);
        g_WPH[i] = hi;
        g_WPL[i] = lo;
    }
}

// ---------------- kernel 1: nei(SIMT fp32) + GNN via split-bf16 mma ------
// smem words: sA 3200 | sX 5120 | sCPH 80x68 | sCPL 80x68 | sWPH 64x68 | sWPL 64x68
#define SMF_A    0
#define SMF_X    3200
#define SMF_CPH  8320
#define SMF_CPL  13760
#define SMF_WPH  19200
#define SMF_WPL  23552
#define SMF_WORDS 27904
#define SM_FWD_BYTES (SMF_WORDS*4)
__global__ __launch_bounds__(256, 2)
void k_forward(const float* __restrict__ x) {
    extern __shared__ float sm[];
    float*    sA   = sm + SMF_A;
    float*    sX   = sm + SMF_X;
    uint32_t* sCPH = (uint32_t*)(sm + SMF_CPH);
    uint32_t* sCPL = (uint32_t*)(sm + SMF_CPL);
    uint32_t* sWPH = (uint32_t*)(sm + SMF_WPH);
    uint32_t* sWPL = (uint32_t*)(sm + SMF_WPL);

    int tid  = threadIdx.x;
    int wid  = tid >> 5, lane = tid & 31;
    int g    = lane >> 2, tg = lane & 3;
    int b0   = blockIdx.x * CHUNK;

    for (int i = tid; i < 3200; i += 256) sA[i] = g_A[i];
    const float* xb = x + (size_t)b0 * NF * DD;
    for (int i = tid; i < 5120; i += 256) sX[i] = xb[i];
    __syncthreads();

    for (int t = 0; t < TT; ++t) {
        // ---- stage W split-bf16 pairs (stride 68 words) ----
        for (int idx = tid; idx < 1024; idx += 256) {
            int p = idx >> 4, dq = (idx & 15) * 4;
            *(uint4*)(sWPH + p*68 + dq) = *(const uint4*)(g_WPH + t*4096 + p*64 + dq);
            *(uint4*)(sWPL + p*68 + dq) = *(const uint4*)(g_WPL + t*4096 + p*64 + dq);
        }
        // ---- lower half of cat: x * s_lo -> split-bf16 pairs ----
        for (int idx = tid; idx < 1280; idx += 256) {
            int row = idx >> 4, q = idx & 15;
            int n = row - (row / 40) * 40;
            float4 xv = *(const float4*)(sX + row*64 + q*4);
            float4 sv = __ldg((const float4*)(g_S + t*NF*128 + n*128 + q*4));
            uint32_t h0, l0, h1, l1;
            splitpk(xv.x*sv.x, xv.y*sv.y, h0, l0);
            splitpk(xv.z*sv.z, xv.w*sv.w, h1, l1);
            *(uint2*)(sCPH + row*68 + q*2) = make_uint2(h0, h1);
            *(uint2*)(sCPL + row*68 + q*2) = make_uint2(l0, l1);
        }
        // ---- phase A (fp32 SIMT): nei * s_hi -> upper pairs ----
        const float* At = sA + t * NF * NF;
        for (int tile = tid; tile < 320; tile += 256) {
            int c  = tile / 160;
            int r  = tile - c * 160;
            int ng = r >> 4;
            int dg = r & 15;
            u64 acc2[4][2];
            #pragma unroll
            for (int k = 0; k < 4; ++k) { acc2[k][0] = 0ull; acc2[k][1] = 0ull; }
            const float* xp = sX + c*2560 + dg*4;
            const float* ap = At + ng*4;
            #pragma unroll 5
            for (int m = 0; m < NF; ++m) {
                ulonglong2 xv = *(const ulonglong2*)(xp + m*64);
                float4 av = *(const float4*)(ap + m*NF);
                u64 a0 = bcast2(av.x), a1 = bcast2(av.y);
                u64 a2 = bcast2(av.z), a3 = bcast2(av.w);
                ffma2(acc2[0][0], a0, xv.x); ffma2(acc2[0][1], a0, xv.y);
                ffma2(acc2[1][0], a1, xv.x); ffma2(acc2[1][1], a1, xv.y);
                ffma2(acc2[2][0], a2, xv.x); ffma2(acc2[2][1], a2, xv.y);
                ffma2(acc2[3][0], a3, xv.x); ffma2(acc2[3][1], a3, xv.y);
            }
            #pragma unroll
            for (int k = 0; k < 4; ++k) {
                int n = ng*4 + k;
                ulonglong2 sv = *(const ulonglong2*)(&__ldg((const float4*)(g_S + t*NF*128 + n*128 + 64 + dg*4)));
                // note: __ldg returns by value; take address via temp
                float4 svf = __ldg((const float4*)(g_S + t*NF*128 + n*128 + 64 + dg*4));
                float2 p01 = unpk(mul2(acc2[k][0], *(u64*)&svf.x));
                float2 p23 = unpk(mul2(acc2[k][1], *(u64*)&svf.z));
                uint32_t h0, l0, h1, l1;
                splitpk(p01.x, p01.y, h0, l0);
                splitpk(p23.x, p23.y, h1, l1);
                int row = c*40 + n;
                *(uint2*)(sCPH + row*68 + 32 + dg*2) = make_uint2(h0, h1);
                *(uint2*)(sCPL + row*68 + 32 + dg*2) = make_uint2(l0, l1);
            }
        }
        __syncthreads();

        // ---- phase B: h[80 x 64] = cat[80 x 128] @ W[128 x 64] via mma ----
        // warp wid owns n8-block (cols wid*8..wid*8+7), all 5 m16 tiles.
        float acc[5][4];
        #pragma unroll
        for (int m = 0; m < 5; ++m)
            #pragma unroll
            for (int j = 0; j < 4; ++j) acc[m][j] = 0.f;

        #pragma unroll
        for (int s = 0; s < 8; ++s) {
            int pb0 = (8*s + tg)*68     + wid*8 + g;
            int pb1 = (8*s + tg + 4)*68 + wid*8 + g;
            uint32_t b0h = sWPH[pb0], b1h = sWPH[pb1];
            uint32_t b0l = sWPL[pb0], b1l = sWPL[pb1];
            #pragma unroll
            for (int m = 0; m < 5; ++m) {
                int ra = (m*16 + g)*68     + 8*s + tg;
                int rb = (m*16 + 8 + g)*68 + 8*s + tg;
                uint32_t a0h = sCPH[ra], a1h = sCPH[rb], a2h = sCPH[ra+4], a3h = sCPH[rb+4];
                uint32_t a0l = sCPL[ra], a1l = sCPL[rb], a2l = sCPL[ra+4], a3l = sCPL[rb+4];
                mma_bf16(acc[m], a0h, a1h, a2h, a3h, b0h, b1h);
                mma_bf16(acc[m], a0h, a1h, a2h, a3h, b0l, b1l);
                mma_bf16(acc[m], a0l, a1l, a2l, a3l, b0h, b1h);
            }
        }

        // ---- epilogue: + bias -> g_H ----
        {
            int d = wid*8 + tg*2;
            #pragma unroll
            for (int m = 0; m < 5; ++m) {
                int r0 = m*16 + g;
                int r1 = r0 + 8;
                int c0r = r0 / 40, n0 = r0 - c0r*40;
                float2 bp0 = *(const float2*)(g_BP + t*2560 + n0*64 + d);
                float* h0p = g_H + ((((size_t)(b0 + c0r)*TT + t)*NF + n0) * DD) + d;
                *(float2*)h0p = make_float2(acc[m][0] + bp0.x, acc[m][1] + bp0.y);
                int c1r = r1 / 40, n1 = r1 - c1r*40;
                float2 bp1 = *(const float2*)(g_BP + t*2560 + n1*64 + d);
                float* h1p = g_H + ((((size_t)(b0 + c1r)*TT + t)*NF + n1) * DD) + d;
                *(float2*)h1p = make_float2(acc[m][2] + bp1.x, acc[m][3] + bp1.y);
            }
        }
        __syncthreads();   // smem reused next t
    }
}

// ---------------- kernel 2: gate GEMM + softmax + pooled output ----------
#define GT_TM 64
#define GSTR  68
#define GH_SZ (GT_TM*GSTR)
#define GG_SZ (NF*GSTR)
#define GDYN_FLOATS (2*GH_SZ + 2*GG_SZ)
__global__ __launch_bounds__(128)
void k_gate(const float* __restrict__ gate_b, float* __restrict__ out) {
    extern __shared__ float gsm[];
    int tid  = threadIdx.x;
    int row0 = blockIdx.x * GT_TM;
    int rg = tid >> 3;
    int cg = tid & 7;

    u64 acc[4][5];
    #pragma unroll
    for (int i = 0; i < 4; ++i)
        #pragma unroll
        for (int j = 0; j < 5; ++j) acc[i][j] = 0ull;

    {
        float* sH = gsm;
        float* sG = gsm + 2*GH_SZ;
        #pragma unroll
        for (int q = 0; q < 8; ++q) {
            int idx = tid + q*128;
            int r = idx >> 4, kq = idx & 15;
            *(float4*)(sH + r*GSTR + kq*4) =
                *(const float4*)(g_H + (size_t)(row0 + r)*2560 + kq*4);
        }
        #pragma unroll
        for (int q = 0; q < 5; ++q) {
            int idx = tid + q*128;
            if (idx < 640) {
                int c = idx >> 4, kq = idx & 15;
                *(float4*)(sG + c*GSTR + kq*4) =
                    *(const float4*)(g_GT + (size_t)c*2560 + kq*4);
            }
        }
    }
    __syncthreads();

    for (int ck = 0; ck < 40; ++ck) {
        int cur = ck & 1;
        float* sH = gsm + cur*GH_SZ;
        float* sG = gsm + 2*GH_SZ + cur*GG_SZ;
        float* nH = gsm + (cur^1)*GH_SZ;
        float* nG = gsm + 2*GH_SZ + (cur^1)*GG_SZ;

        float4 hreg[8], greg[5];
        bool more = (ck + 1) < 40;
        if (more) {
            int k0n = (ck + 1) * 64;
            #pragma unroll
            for (int q = 0; q < 8; ++q) {
                int idx = tid + q*128;
                int r = idx >> 4, kq = idx & 15;
                hreg[q] = *(const float4*)(g_H + (size_t)(row0 + r)*2560 + k0n + kq*4);
            }
            #pragma unroll
            for (int q = 0; q < 5; ++q) {
                int idx = tid + q*128;
                if (idx < 640) {
                    int c = idx >> 4, kq = idx & 15;
                    greg[q] = *(const float4*)(g_GT + (size_t)c*2560 + k0n + kq*4);
                }
            }
        }

        #pragma unroll
        for (int k4 = 0; k4 < 16; ++k4) {
            ulonglong2 hv[4], gv[5];
            #pragma unroll
            for (int i = 0; i < 4; ++i)
                hv[i] = *(const ulonglong2*)(sH + (rg*4 + i)*GSTR + k4*4);
            #pragma unroll
            for (int j = 0; j < 5; ++j)
                gv[j] = *(const ulonglong2*)(sG + (cg*5 + j)*GSTR + k4*4);
            #pragma unroll
            for (int i = 0; i < 4; ++i)
                #pragma unroll
                for (int j = 0; j < 5; ++j) {
                    ffma2(acc[i][j], hv[i].x, gv[j].x);
                    ffma2(acc[i][j], hv[i].y, gv[j].y);
                }
        }

        if (more) {
            #pragma unroll
            for (int q = 0; q < 8; ++q) {
                int idx = tid + q*128;
                int r = idx >> 4, kq = idx & 15;
                *(float4*)(nH + r*GSTR + kq*4) = hreg[q];
            }
            #pragma unroll
            for (int q = 0; q < 5; ++q) {
                int idx = tid + q*128;
                if (idx < 640) {
                    int c = idx >> 4, kq = idx & 15;
                    *(float4*)(nG + c*GSTR + kq*4) = greg[q];
                }
            }
        }
        __syncthreads();
    }

    #pragma unroll
    for (int i = 0; i < 4; ++i)
        #pragma unroll
        for (int j = 0; j < 5; ++j) {
            float2 p = unpk(acc[i][j]);
            gsm[(rg*4 + i)*41 + cg*5 + j] = p.x + p.y + __ldg(gate_b + cg*5 + j);
        }
    __syncthreads();

    if (tid < GT_TM) {
        float* lp = gsm + tid*41;
        float mx = -1e30f;
        #pragma unroll 8
        for (int n = 0; n < NF; ++n) mx = fmaxf(mx, lp[n]);
        float se = 0.f;
        #pragma unroll 8
        for (int n = 0; n < NF; ++n) se += expf(lp[n] - mx);
        float inv = 1.f / se;
        #pragma unroll 8
        for (int n = 0; n < NF; ++n) lp[n] = expf(lp[n] - mx) * inv;
    }
    __syncthreads();

    {
        int row = tid >> 1;
        int off = (tid & 1) * 32;
        const float* hp = g_H + (size_t)(row0 + row)*2560 + off;
        const float* wp = gsm + row*41;
        float4 a[8];
        #pragma unroll
        for (int q = 0; q < 8; ++q) a[q] = make_float4(0.f, 0.f, 0.f, 0.f);
        #pragma unroll 4
        for (int n = 0; n < NF; ++n) {
            float wv = wp[n];
            const float4* h4 = (const float4*)(hp + n*64);
            #pragma unroll
            for (int q = 0; q < 8; ++q) {
                float4 hv = h4[q];
                a[q].x += wv * hv.x;
                a[q].y += wv * hv.y;
                a[q].z += wv * hv.z;
                a[q].w += wv * hv.w;
            }
        }
        float* op = out + (size_t)(row0 + row)*64 + off;
        #pragma unroll
        for (int q = 0; q < 8; ++q) *(float4*)(op + q*4) = a[q];
    }
}

// ---------------- launcher ------------------------------------------------
extern "C" void kernel_launch(void* const* d_in, const int* in_sizes, int n_in,
                              void* d_out, int out_size) {
    const float* x        = (const float*)d_in[0];
    const float* masker   = (const float*)d_in[1];
    const float* ln_gamma = (const float*)d_in[2];
    const float* ln_beta  = (const float*)d_in[3];
    const float* gnn_w    = (const float*)d_in[4];
    const float* gnn_b    = (const float*)d_in[5];
    const float* bn_gamma = (const float*)d_in[6];
    const float* bn_beta  = (const float*)d_in[7];
    const float* bn_mean  = (const float*)d_in[8];
    const float* bn_var   = (const float*)d_in[9];
    const float* gate_w   = (const float*)d_in[10];
    const float* gate_b   = (const float*)d_in[11];
    float* out = (float*)d_out;

    cudaFuncSetAttribute(k_forward, cudaFuncAttributeMaxDynamicSharedMemorySize,
                         SM_FWD_BYTES);
    cudaFuncSetAttribute(k_gate, cudaFuncAttributeMaxDynamicSharedMemorySize,
                         GDYN_FLOATS * (int)sizeof(float));

    prep_adj<<<2, 256>>>(masker, ln_gamma, ln_beta);
    prep_sbp<<<80, 128>>>(bn_gamma, bn_beta, bn_mean, bn_var, gnn_w, gnn_b);
    prep_gt<<<(NF*2560 + 255)/256, 256>>>(gate_w);
    prep_wp<<<(TT*64*64 + 255)/256, 256>>>(gnn_w);
    k_forward<<<BSZ / CHUNK, 256, SM_FWD_BYTES>>>(x);
    k_gate<<<BSZ * TT / GT_TM, 128, GDYN_FLOATS * sizeof(float)>>>(gate_b, out);
}

// round 9
// speedup vs baseline: 2.0201x; 1.0777x over previous
#include <cuda_runtime.h>
#include <cuda_bf16.h>
#include <math.h>
#include <stdint.h>

#define BSZ   8192
#define TT    2
#define NF    40
#define DD    64
#define FEPS  1e-5f
#define CHUNK 2

typedef unsigned long long u64;

// ---- packed f32x2 helpers ----
__device__ __forceinline__ void ffma2(u64& d, u64 a, u64 b) {
    asm("fma.rn.f32x2 %0, %1, %2, %0;" : "+l"(d) : "l"(a), "l"(b));
}
__device__ __forceinline__ u64 mul2(u64 a, u64 b) {
    u64 r; asm("mul.rn.f32x2 %0, %1, %2;" : "=l"(r) : "l"(a), "l"(b)); return r;
}
__device__ __forceinline__ u64 bcast2(float v) {
    u64 r; asm("mov.b64 %0, {%1, %1};" : "=l"(r) : "f"(v)); return r;
}
__device__ __forceinline__ float2 unpk(u64 v) {
    float2 r; asm("mov.b64 {%0, %1}, %2;" : "=f"(r.x), "=f"(r.y) : "l"(v)); return r;
}

// ---- split-bf16: (a,b) -> hi pair + residual pair ----
__device__ __forceinline__ void splitpk(float a, float b, uint32_t& hi, uint32_t& lo) {
    __nv_bfloat162 h = __floats2bfloat162_rn(a, b);
    float ra = a - __bfloat162float(h.x);
    float rb = b - __bfloat162float(h.y);
    __nv_bfloat162 l = __floats2bfloat162_rn(ra, rb);
    hi = *reinterpret_cast<uint32_t*>(&h);
    lo = *reinterpret_cast<uint32_t*>(&l);
}
// reconstruct two floats from hi/lo bf16x2 pairs
__device__ __forceinline__ float2 rec2(uint32_t h, uint32_t l) {
    float2 hf = __bfloat1622float2(*reinterpret_cast<__nv_bfloat162*>(&h));
    float2 lf = __bfloat1622float2(*reinterpret_cast<__nv_bfloat162*>(&l));
    return make_float2(hf.x + lf.x, hf.y + lf.y);
}

// ---- legacy tensor core mma (sm_80+) ----
__device__ __forceinline__ void mma_bf16(float* d,
    uint32_t a0, uint32_t a1, uint32_t a2, uint32_t a3,
    uint32_t b0, uint32_t b1) {
    asm volatile(
        "mma.sync.aligned.m16n8k16.row.col.f32.bf16.bf16.f32 "
        "{%0,%1,%2,%3}, {%4,%5,%6,%7}, {%8,%9}, {%0,%1,%2,%3};"
        : "+f"(d[0]), "+f"(d[1]), "+f"(d[2]), "+f"(d[3])
        : "r"(a0), "r"(a1), "r"(a2), "r"(a3), "r"(b0), "r"(b1));
}

// ---- cp.async (sm_80+) ----
__device__ __forceinline__ uint32_t smem_u32(const void* p) {
    uint32_t a;
    asm("{ .reg .u64 t; cvta.to.shared.u64 t, %1; cvt.u32.u64 %0, t; }" : "=r"(a) : "l"(p));
    return a;
}
__device__ __forceinline__ void cpa16(uint32_t dst, const void* src) {
    asm volatile("cp.async.cg.shared.global [%0], [%1], 16;" :: "r"(dst), "l"(src));
}
#define CPA_COMMIT() asm volatile("cp.async.commit_group;" ::: "memory")
#define CPA_WAIT(n)  asm volatile("cp.async.wait_group %0;" :: "n"(n) : "memory")

// ---------------- device scratch ----------------
__device__ float g_A [TT*NF*NF];
__device__ float g_S [TT*NF*128];
__device__ float g_BP[TT*NF*DD];
__device__ float g_GT[NF*NF*DD];                    // (unused placeholder kept small)
__device__ uint32_t g_WPH[TT*64*64];                // W split pairs
__device__ uint32_t g_WPL[TT*64*64];
__device__ uint32_t g_HH[(size_t)BSZ*TT*1280];      // h hi pairs: [row][k/2]
__device__ uint32_t g_HL[(size_t)BSZ*TT*1280];      // h lo pairs
__device__ uint32_t g_GPH[NF*1280];                 // gate_w split pairs: [n'][k/2]
__device__ uint32_t g_GPL[NF*1280];

// ---------------- prep 1: adjacency -> LN -> mask -> softmax -> A --------
__global__ void prep_adj(const float* __restrict__ masker,
                         const float* __restrict__ ln_gamma,
                         const float* __restrict__ ln_beta) {
    int t = blockIdx.x;
    __shared__ float sadj[NF*NF];
    int tid = threadIdx.x;
    const float* mk = masker + (size_t)t * 3 * NF * NF;
    for (int i = tid; i < NF*NF; i += blockDim.x) {
        float p = mk[i] * mk[NF*NF + i] * mk[2*NF*NF + i];
        sadj[i] = p > 0.f ? p : 0.f;
    }
    __syncthreads();
    if (tid < NF) {
        int j = tid;
        float sum = 0.f, sq = 0.f;
        for (int i = 0; i < NF; ++i) { float a = sadj[i*NF + j]; sum += a; sq += a*a; }
        float mu  = sum * (1.f/NF);
        float var = sq * (1.f/NF) - mu*mu;
        float rs  = rsqrtf(var + FEPS);
        float xm[NF];
        float mx = -1e30f;
        for (int i = 0; i < NF; ++i) {
            float a   = sadj[i*NF + j];
            float msk = (a != 0.f) ? 1.f : 0.f;
            float v   = (a - mu) * rs * ln_gamma[i] + ln_beta[i];
            v += (1.f - msk) * (-1e9f);
            if (i == j) v += 1.f;
            xm[i] = v;
            mx = fmaxf(mx, v);
        }
        float se = 0.f;
        for (int i = 0; i < NF; ++i) { xm[i] = expf(xm[i] - mx); se += xm[i]; }
        float inv = 1.f / se;
        for (int i = 0; i < NF; ++i) {
            float a   = sadj[i*NF + j];
            float msk = (a != 0.f) ? 1.f : 0.f;
            g_A[t*NF*NF + i*NF + j] = xm[i] * inv * msk;
        }
    }
}

// ---------------- prep 2: fold BN into scale s and bias b' ---------------
__global__ void prep_sbp(const float* __restrict__ bn_gamma,
                         const float* __restrict__ bn_beta,
                         const float* __restrict__ bn_mean,
                         const float* __restrict__ bn_var,
                         const float* __restrict__ gnn_w,
                         const float* __restrict__ gnn_b) {
    int blk = blockIdx.x;          // t*40 + n
    int t = blk / NF, n = blk - t*NF;
    __shared__ float so[128];
    int tid = threadIdx.x;
    int F = blk*128 + tid;
    float s = bn_gamma[F] * rsqrtf(bn_var[F] + FEPS);
    float o = bn_beta[F] - bn_mean[F] * s;
    g_S[blk*128 + tid] = s;
    so[tid] = o;
    __syncthreads();
    if (tid < DD) {
        float acc = gnn_b[t*NF*DD + n*DD + tid];
        #pragma unroll 8
        for (int f = 0; f < 128; ++f)
            acc += so[f] * gnn_w[t*128*DD + f*DD + tid];
        g_BP[blk*DD + tid] = acc;
    }
}

// ---------------- prep 4: W -> split-bf16 pair layout --------------------
__global__ void prep_wp(const float* __restrict__ gnn_w) {
    int i = blockIdx.x * 256 + threadIdx.x;   // t*4096 + p*64 + d
    if (i < TT*64*64) {
        int t = i >> 12, r = i & 4095;
        int p = r >> 6, d = r & 63;
        float w0 = gnn_w[t*8192 + (2*p)*64 + d];
        float w1 = gnn_w[t*8192 + (2*p+1)*64 + d];
        uint32_t hi, lo;
        splitpk(w0, w1, hi, lo);
        g_WPH[i] = hi;
        g_WPL[i] = lo;
    }
}

// ---------------- prep 5: gate_w -> split pairs [n'][k/2] ----------------
__global__ void prep_gp(const float* __restrict__ gate_w) {
    int i = blockIdx.x * 256 + threadIdx.x;   // c*1280 + p
    if (i < NF * 1280) {
        int c = i / 1280, p = i - c*1280;
        float w0 = gate_w[(2*p)*NF + c];
        float w1 = gate_w[(2*p+1)*NF + c];
        uint32_t hi, lo;
        splitpk(w0, w1, hi, lo);
        g_GPH[i] = hi;
        g_GPL[i] = lo;
    }
}

// ---------------- kernel 1: nei(SIMT fp32) + GNN via split-bf16 mma ------
#define SMF_A    0
#define SMF_X    3200
#define SMF_CPH  8320
#define SMF_CPL  13760
#define SMF_WPH  19200
#define SMF_WPL  23552
#define SMF_WORDS 27904
#define SM_FWD_BYTES (SMF_WORDS*4)
__global__ __launch_bounds__(256, 2)
void k_forward(const float* __restrict__ x) {
    extern __shared__ float sm[];
    float*    sA   = sm + SMF_A;
    float*    sX   = sm + SMF_X;
    uint32_t* sCPH = (uint32_t*)(sm + SMF_CPH);
    uint32_t* sCPL = (uint32_t*)(sm + SMF_CPL);
    uint32_t* sWPH = (uint32_t*)(sm + SMF_WPH);
    uint32_t* sWPL = (uint32_t*)(sm + SMF_WPL);

    int tid  = threadIdx.x;
    int wid  = tid >> 5, lane = tid & 31;
    int g    = lane >> 2, tg = lane & 3;
    int b0   = blockIdx.x * CHUNK;

    for (int i = tid; i < 3200; i += 256) sA[i] = g_A[i];
    const float* xb = x + (size_t)b0 * NF * DD;
    for (int i = tid; i < 5120; i += 256) sX[i] = xb[i];
    __syncthreads();

    for (int t = 0; t < TT; ++t) {
        for (int idx = tid; idx < 1024; idx += 256) {
            int p = idx >> 4, dq = (idx & 15) * 4;
            *(uint4*)(sWPH + p*68 + dq) = *(const uint4*)(g_WPH + t*4096 + p*64 + dq);
            *(uint4*)(sWPL + p*68 + dq) = *(const uint4*)(g_WPL + t*4096 + p*64 + dq);
        }
        for (int idx = tid; idx < 1280; idx += 256) {
            int row = idx >> 4, q = idx & 15;
            int n = row - (row / 40) * 40;
            float4 xv = *(const float4*)(sX + row*64 + q*4);
            float4 sv = __ldg((const float4*)(g_S + t*NF*128 + n*128 + q*4));
            uint32_t h0, l0, h1, l1;
            splitpk(xv.x*sv.x, xv.y*sv.y, h0, l0);
            splitpk(xv.z*sv.z, xv.w*sv.w, h1, l1);
            *(uint2*)(sCPH + row*68 + q*2) = make_uint2(h0, h1);
            *(uint2*)(sCPL + row*68 + q*2) = make_uint2(l0, l1);
        }
        const float* At = sA + t * NF * NF;
        for (int tile = tid; tile < 320; tile += 256) {
            int c  = tile / 160;
            int r  = tile - c * 160;
            int ng = r >> 4;
            int dg = r & 15;
            u64 acc2[4][2];
            #pragma unroll
            for (int k = 0; k < 4; ++k) { acc2[k][0] = 0ull; acc2[k][1] = 0ull; }
            const float* xp = sX + c*2560 + dg*4;
            const float* ap = At + ng*4;
            #pragma unroll 5
            for (int m = 0; m < NF; ++m) {
                ulonglong2 xv = *(const ulonglong2*)(xp + m*64);
                float4 av = *(const float4*)(ap + m*NF);
                u64 a0 = bcast2(av.x), a1 = bcast2(av.y);
                u64 a2 = bcast2(av.z), a3 = bcast2(av.w);
                ffma2(acc2[0][0], a0, xv.x); ffma2(acc2[0][1], a0, xv.y);
                ffma2(acc2[1][0], a1, xv.x); ffma2(acc2[1][1], a1, xv.y);
                ffma2(acc2[2][0], a2, xv.x); ffma2(acc2[2][1], a2, xv.y);
                ffma2(acc2[3][0], a3, xv.x); ffma2(acc2[3][1], a3, xv.y);
            }
            #pragma unroll
            for (int k = 0; k < 4; ++k) {
                int n = ng*4 + k;
                float4 svf = __ldg((const float4*)(g_S + t*NF*128 + n*128 + 64 + dg*4));
                float2 p01 = unpk(mul2(acc2[k][0], *(u64*)&svf.x));
                float2 p23 = unpk(mul2(acc2[k][1], *(u64*)&svf.z));
                uint32_t h0, l0, h1, l1;
                splitpk(p01.x, p01.y, h0, l0);
                splitpk(p23.x, p23.y, h1, l1);
                int row = c*40 + n;
                *(uint2*)(sCPH + row*68 + 32 + dg*2) = make_uint2(h0, h1);
                *(uint2*)(sCPL + row*68 + 32 + dg*2) = make_uint2(l0, l1);
            }
        }
        __syncthreads();

        // phase B MMA: h[80x64] = cat[80x128] @ W[128x64]
        float acc[5][4];
        #pragma unroll
        for (int m = 0; m < 5; ++m)
            #pragma unroll
            for (int j = 0; j < 4; ++j) acc[m][j] = 0.f;

        #pragma unroll
        for (int s = 0; s < 8; ++s) {
            int pb0 = (8*s + tg)*68     + wid*8 + g;
            int pb1 = (8*s + tg + 4)*68 + wid*8 + g;
            uint32_t b0h = sWPH[pb0], b1h = sWPH[pb1];
            uint32_t b0l = sWPL[pb0], b1l = sWPL[pb1];
            #pragma unroll
            for (int m = 0; m < 5; ++m) {
                int ra = (m*16 + g)*68     + 8*s + tg;
                int rb = (m*16 + 8 + g)*68 + 8*s + tg;
                uint32_t a0h = sCPH[ra], a1h = sCPH[rb], a2h = sCPH[ra+4], a3h = sCPH[rb+4];
                uint32_t a0l = sCPL[ra], a1l = sCPL[rb], a2l = sCPL[ra+4], a3l = sCPL[rb+4];
                mma_bf16(acc[m], a0h, a1h, a2h, a3h, b0h, b1h);
                mma_bf16(acc[m], a0h, a1h, a2h, a3h, b0l, b1l);
                mma_bf16(acc[m], a0l, a1l, a2l, a3l, b0h, b1h);
            }
        }

        // epilogue: +bias, split and store h pairs
        {
            int d = wid*8 + tg*2;
            int pq = wid*4 + tg;   // pair offset within n-block
            #pragma unroll
            for (int m = 0; m < 5; ++m) {
                int r0 = m*16 + g;
                int r1 = r0 + 8;
                int c0r = r0 / 40, n0 = r0 - c0r*40;
                float2 bp0 = *(const float2*)(g_BP + t*2560 + n0*64 + d);
                float2 o0 = make_float2(acc[m][0] + bp0.x, acc[m][1] + bp0.y);
                uint32_t h0, l0;
                splitpk(o0.x, o0.y, h0, l0);
                size_t row0i = (size_t)((b0 + c0r)*TT + t) * 1280 + n0*32 + pq;
                g_HH[row0i] = h0; g_HL[row0i] = l0;

                int c1r = r1 / 40, n1 = r1 - c1r*40;
                float2 bp1 = *(const float2*)(g_BP + t*2560 + n1*64 + d);
                float2 o1 = make_float2(acc[m][2] + bp1.x, acc[m][3] + bp1.y);
                uint32_t h1, l1;
                splitpk(o1.x, o1.y, h1, l1);
                size_t row1i = (size_t)((b0 + c1r)*TT + t) * 1280 + n1*32 + pq;
                g_HH[row1i] = h1; g_HL[row1i] = l1;
            }
        }
        __syncthreads();
    }
}

// ---------------- kernel 2: gate via split-bf16 mma + softmax + pool -----
// M-tile 64 rows (4 warps x m16), N = 40 (5 n8 tiles), K = 2560 in 40
// chunks of 64. cp.async double-buffered smem staging.
#define ASTR 36
#define AH_W (64*ASTR)          // 2304 words
#define BH_W (NF*ASTR)          // 1440 words
#define BUF_W (2*AH_W + 2*BH_W) // 7488 words
#define GSM_WORDS (2*BUF_W)     // 14976 words = 59904 B
__device__ __forceinline__ void gate_issue_chunk(uint32_t bufb, int row0, int ck, int tid) {
    #pragma unroll
    for (int q = 0; q < 4; ++q) {
        int idx = tid + q*128;            // 0..511
        int r = idx >> 3, j = idx & 7;
        uint32_t dst = bufb + (uint32_t)(r*ASTR + j*4)*4u;
        const uint32_t* src = g_HH + (size_t)(row0 + r)*1280 + ck*32 + j*4;
        cpa16(dst, src);
        cpa16(dst + AH_W*4u, g_HL + (size_t)(row0 + r)*1280 + ck*32 + j*4);
    }
    #pragma unroll
    for (int q = 0; q < 3; ++q) {
        int idx = tid + q*128;
        if (idx < 320) {
            int c = idx >> 3, j = idx & 7;
            uint32_t dst = bufb + (uint32_t)(2*AH_W + c*ASTR + j*4)*4u;
            cpa16(dst, g_GPH + c*1280 + ck*32 + j*4);
            cpa16(dst + BH_W*4u, g_GPL + c*1280 + ck*32 + j*4);
        }
    }
    CPA_COMMIT();
}
__global__ __launch_bounds__(128)
void k_gate(const float* __restrict__ gate_b, float* __restrict__ out) {
    extern __shared__ uint32_t gw[];
    uint32_t gb = smem_u32(gw);
    int tid  = threadIdx.x;
    int wid  = tid >> 5, lane = tid & 31;
    int g    = lane >> 2, tg = lane & 3;
    int row0 = blockIdx.x * 64;

    float acc[5][4];
    #pragma unroll
    for (int m = 0; m < 5; ++m)
        #pragma unroll
        for (int j = 0; j < 4; ++j) acc[m][j] = 0.f;

    gate_issue_chunk(gb, row0, 0, tid);

    for (int ck = 0; ck < 40; ++ck) {
        int cur = ck & 1;
        bool more = (ck + 1) < 40;
        if (more) gate_issue_chunk(gb + (cur^1)*BUF_W*4u, row0, ck + 1, tid);
        if (more) { CPA_WAIT(1); } else { CPA_WAIT(0); }
        __syncthreads();

        const uint32_t* Ah = gw + cur*BUF_W;
        const uint32_t* Al = Ah + AH_W;
        const uint32_t* Bh = Ah + 2*AH_W;
        const uint32_t* Bl = Bh + BH_W;

        #pragma unroll
        for (int ks = 0; ks < 4; ++ks) {
            int ko = ks*8;
            int ra = (wid*16 + g)*ASTR + ko + tg;
            int rb = (wid*16 + 8 + g)*ASTR + ko + tg;
            uint32_t a0h = Ah[ra], a1h = Ah[rb], a2h = Ah[ra+4], a3h = Ah[rb+4];
            uint32_t a0l = Al[ra], a1l = Al[rb], a2l = Al[ra+4], a3l = Al[rb+4];
            #pragma unroll
            for (int nt = 0; nt < 5; ++nt) {
                int pb = (nt*8 + g)*ASTR + ko + tg;
                uint32_t b0h = Bh[pb], b1h = Bh[pb+4];
                uint32_t b0l = Bl[pb], b1l = Bl[pb+4];
                mma_bf16(acc[nt], a0h, a1h, a2h, a3h, b0h, b1h);
                mma_bf16(acc[nt], a0h, a1h, a2h, a3h, b0l, b1l);
                mma_bf16(acc[nt], a0l, a1l, a2l, a3l, b0h, b1h);
            }
        }
        __syncthreads();
    }

    // logits -> smem [64][41]
    float* sL = (float*)gw;
    #pragma unroll
    for (int nt = 0; nt < 5; ++nt) {
        int col = nt*8 + tg*2;
        float b0 = __ldg(gate_b + col);
        float b1 = __ldg(gate_b + col + 1);
        sL[(wid*16 + g)*41 + col]         = acc[nt][0] + b0;
        sL[(wid*16 + g)*41 + col + 1]     = acc[nt][1] + b1;
        sL[(wid*16 + 8 + g)*41 + col]     = acc[nt][2] + b0;
        sL[(wid*16 + 8 + g)*41 + col + 1] = acc[nt][3] + b1;
    }
    __syncthreads();

    if (tid < 64) {
        float* lp = sL + tid*41;
        float mx = -1e30f;
        #pragma unroll 8
        for (int n = 0; n < NF; ++n) mx = fmaxf(mx, lp[n]);
        float se = 0.f;
        #pragma unroll 8
        for (int n = 0; n < NF; ++n) se += expf(lp[n] - mx);
        float inv = 1.f / se;
        #pragma unroll 8
        for (int n = 0; n < NF; ++n) lp[n] = expf(lp[n] - mx) * inv;
    }
    __syncthreads();

    // pool: out[row][d] = sum_n w[n] * (hi+lo)[row][n*64+d]  (L2-hot)
    {
        int row = tid >> 1;
        int pb  = (tid & 1) * 16;         // pair offset within n-block
        const uint32_t* hh = g_HH + (size_t)(row0 + row)*1280 + pb;
        const uint32_t* hl = g_HL + (size_t)(row0 + row)*1280 + pb;
        const float* wp = sL + row*41;
        float2 a2[16];
        #pragma unroll
        for (int q = 0; q < 16; ++q) a2[q] = make_float2(0.f, 0.f);
        #pragma unroll 4
        for (int n = 0; n < NF; ++n) {
            float wv = wp[n];
            #pragma unroll
            for (int q4 = 0; q4 < 4; ++q4) {
                uint4 hv = *(const uint4*)(hh + n*32 + q4*4);
                uint4 lv = *(const uint4*)(hl + n*32 + q4*4);
                float2 f0 = rec2(hv.x, lv.x), f1 = rec2(hv.y, lv.y);
                float2 f2 = rec2(hv.z, lv.z), f3 = rec2(hv.w, lv.w);
                a2[q4*4+0].x += wv*f0.x; a2[q4*4+0].y += wv*f0.y;
                a2[q4*4+1].x += wv*f1.x; a2[q4*4+1].y += wv*f1.y;
                a2[q4*4+2].x += wv*f2.x; a2[q4*4+2].y += wv*f2.y;
                a2[q4*4+3].x += wv*f3.x; a2[q4*4+3].y += wv*f3.y;
            }
        }
        float* op = out + (size_t)(row0 + row)*64 + (tid & 1)*32;
        #pragma unroll
        for (int q = 0; q < 8; ++q)
            *(float4*)(op + q*4) = make_float4(a2[q*2].x, a2[q*2].y, a2[q*2+1].x, a2[q*2+1].y);
    }
}

// ---------------- launcher ------------------------------------------------
extern "C" void kernel_launch(void* const* d_in, const int* in_sizes, int n_in,
                              void* d_out, int out_size) {
    const float* x        = (const float*)d_in[0];
    const float* masker   = (const float*)d_in[1];
    const float* ln_gamma = (const float*)d_in[2];
    const float* ln_beta  = (const float*)d_in[3];
    const float* gnn_w    = (const float*)d_in[4];
    const float* gnn_b    = (const float*)d_in[5];
    const float* bn_gamma = (const float*)d_in[6];
    const float* bn_beta  = (const float*)d_in[7];
    const float* bn_mean  = (const float*)d_in[8];
    const float* bn_var   = (const float*)d_in[9];
    const float* gate_w   = (const float*)d_in[10];
    const float* gate_b   = (const float*)d_in[11];
    float* out = (float*)d_out;

    cudaFuncSetAttribute(k_forward, cudaFuncAttributeMaxDynamicSharedMemorySize,
                         SM_FWD_BYTES);
    cudaFuncSetAttribute(k_gate, cudaFuncAttributeMaxDynamicSharedMemorySize,
                         GSM_WORDS * (int)sizeof(uint32_t));

    prep_adj<<<2, 256>>>(masker, ln_gamma, ln_beta);
    prep_sbp<<<80, 128>>>(bn_gamma, bn_beta, bn_mean, bn_var, gnn_w, gnn_b);
    prep_wp<<<(TT*64*64 + 255)/256, 256>>>(gnn_w);
    prep_gp<<<(NF*1280 + 255)/256, 256>>>(gate_w);
    k_forward<<<BSZ / CHUNK, 256, SM_FWD_BYTES>>>(x);
    k_gate<<<BSZ * TT / 64, 128, GSM_WORDS * sizeof(uint32_t)>>>(gate_b, out);
}

// round 10
// speedup vs baseline: 2.3421x; 1.1594x over previous
#include <cuda_runtime.h>
#include <cuda_bf16.h>
#include <math.h>
#include <stdint.h>

#define BSZ   8192
#define TT    2
#define NF    40
#define DD    64
#define FEPS  1e-5f
#define CHUNK 2

typedef unsigned long long u64;

// ---- split-bf16: (a,b) -> hi pair + residual pair ----
__device__ __forceinline__ void splitpk(float a, float b, uint32_t& hi, uint32_t& lo) {
    __nv_bfloat162 h = __floats2bfloat162_rn(a, b);
    float ra = a - __bfloat162float(h.x);
    float rb = b - __bfloat162float(h.y);
    __nv_bfloat162 l = __floats2bfloat162_rn(ra, rb);
    hi = *reinterpret_cast<uint32_t*>(&h);
    lo = *reinterpret_cast<uint32_t*>(&l);
}
__device__ __forceinline__ float2 rec2(uint32_t h, uint32_t l) {
    float2 hf = __bfloat1622float2(*reinterpret_cast<__nv_bfloat162*>(&h));
    float2 lf = __bfloat1622float2(*reinterpret_cast<__nv_bfloat162*>(&l));
    return make_float2(hf.x + lf.x, hf.y + lf.y);
}

// ---- legacy tensor core mma (sm_80+) ----
__device__ __forceinline__ void mma_bf16(float* d,
    uint32_t a0, uint32_t a1, uint32_t a2, uint32_t a3,
    uint32_t b0, uint32_t b1) {
    asm volatile(
        "mma.sync.aligned.m16n8k16.row.col.f32.bf16.bf16.f32 "
        "{%0,%1,%2,%3}, {%4,%5,%6,%7}, {%8,%9}, {%0,%1,%2,%3};"
        : "+f"(d[0]), "+f"(d[1]), "+f"(d[2]), "+f"(d[3])
        : "r"(a0), "r"(a1), "r"(a2), "r"(a3), "r"(b0), "r"(b1));
}

// ---- cp.async (sm_80+) ----
__device__ __forceinline__ uint32_t smem_u32(const void* p) {
    uint32_t a;
    asm("{ .reg .u64 t; cvta.to.shared.u64 t, %1; cvt.u32.u64 %0, t; }" : "=r"(a) : "l"(p));
    return a;
}
__device__ __forceinline__ void cpa16(uint32_t dst, const void* src) {
    asm volatile("cp.async.cg.shared.global [%0], [%1], 16;" :: "r"(dst), "l"(src));
}
#define CPA_COMMIT() asm volatile("cp.async.commit_group;" ::: "memory")
#define CPA_WAIT(n)  asm volatile("cp.async.wait_group %0;" :: "n"(n) : "memory")

// ---------------- device scratch ----------------
__device__ float g_A [TT*NF*NF];
__device__ float g_S [TT*NF*128];
__device__ float g_BP[TT*NF*DD];
__device__ uint32_t g_WPH[TT*64*64];             // W split pairs [t][f/2][d]
__device__ uint32_t g_WPL[TT*64*64];
__device__ uint32_t g_APH[TT*48*24];             // A^T split pairs [t][n(48)][m/2(24)]
__device__ uint32_t g_APL[TT*48*24];
__device__ uint32_t g_HH[(size_t)BSZ*TT*1280];   // h hi pairs [row][k/2]
__device__ uint32_t g_HL[(size_t)BSZ*TT*1280];
__device__ uint32_t g_GPH[NF*1280];              // gate_w split pairs [n'][k/2]
__device__ uint32_t g_GPL[NF*1280];

// ---------------- prep 1: adjacency -> LN -> mask -> softmax -> A --------
__global__ void prep_adj(const float* __restrict__ masker,
                         const float* __restrict__ ln_gamma,
                         const float* __restrict__ ln_beta) {
    int t = blockIdx.x;
    __shared__ float sadj[NF*NF];
    int tid = threadIdx.x;
    const float* mk = masker + (size_t)t * 3 * NF * NF;
    for (int i = tid; i < NF*NF; i += blockDim.x) {
        float p = mk[i] * mk[NF*NF + i] * mk[2*NF*NF + i];
        sadj[i] = p > 0.f ? p : 0.f;
    }
    __syncthreads();
    if (tid < NF) {
        int j = tid;
        float sum = 0.f, sq = 0.f;
        for (int i = 0; i < NF; ++i) { float a = sadj[i*NF + j]; sum += a; sq += a*a; }
        float mu  = sum * (1.f/NF);
        float var = sq * (1.f/NF) - mu*mu;
        float rs  = rsqrtf(var + FEPS);
        float xm[NF];
        float mx = -1e30f;
        for (int i = 0; i < NF; ++i) {
            float a   = sadj[i*NF + j];
            float msk = (a != 0.f) ? 1.f : 0.f;
            float v   = (a - mu) * rs * ln_gamma[i] + ln_beta[i];
            v += (1.f - msk) * (-1e9f);
            if (i == j) v += 1.f;
            xm[i] = v;
            mx = fmaxf(mx, v);
        }
        float se = 0.f;
        for (int i = 0; i < NF; ++i) { xm[i] = expf(xm[i] - mx); se += xm[i]; }
        float inv = 1.f / se;
        for (int i = 0; i < NF; ++i) {
            float a   = sadj[i*NF + j];
            float msk = (a != 0.f) ? 1.f : 0.f;
            g_A[t*NF*NF + i*NF + j] = xm[i] * inv * msk;
        }
    }
}

// ---------------- prep 2: fold BN into scale s and bias b' ---------------
__global__ void prep_sbp(const float* __restrict__ bn_gamma,
                         const float* __restrict__ bn_beta,
                         const float* __restrict__ bn_mean,
                         const float* __restrict__ bn_var,
                         const float* __restrict__ gnn_w,
                         const float* __restrict__ gnn_b) {
    int blk = blockIdx.x;          // t*40 + n
    int t = blk / NF, n = blk - t*NF;
    __shared__ float so[128];
    int tid = threadIdx.x;
    int F = blk*128 + tid;
    float s = bn_gamma[F] * rsqrtf(bn_var[F] + FEPS);
    float o = bn_beta[F] - bn_mean[F] * s;
    g_S[blk*128 + tid] = s;
    so[tid] = o;
    __syncthreads();
    if (tid < DD) {
        float acc = gnn_b[t*NF*DD + n*DD + tid];
        #pragma unroll 8
        for (int f = 0; f < 128; ++f)
            acc += so[f] * gnn_w[t*128*DD + f*DD + tid];
        g_BP[blk*DD + tid] = acc;
    }
}

// ---------------- prep 3: W -> split pairs --------------------------------
__global__ void prep_wp(const float* __restrict__ gnn_w) {
    int i = blockIdx.x * 256 + threadIdx.x;   // t*4096 + p*64 + d
    if (i < TT*64*64) {
        int t = i >> 12, r = i & 4095;
        int p = r >> 6, d = r & 63;
        float w0 = gnn_w[t*8192 + (2*p)*64 + d];
        float w1 = gnn_w[t*8192 + (2*p+1)*64 + d];
        uint32_t hi, lo;
        splitpk(w0, w1, hi, lo);
        g_WPH[i] = hi;
        g_WPL[i] = lo;
    }
}

// ---------------- prep 4: A^T -> split pairs (padded 48x24) --------------
__global__ void prep_ap() {
    int i = blockIdx.x * 256 + threadIdx.x;   // t*1152 + n*24 + p
    if (i < TT*48*24) {
        int t = i / 1152, r = i - t*1152;
        int n = r / 24, p = r - n*24;
        float w0 = (n < NF && 2*p   < NF) ? g_A[t*NF*NF + (2*p)*NF + n]   : 0.f;
        float w1 = (n < NF && 2*p+1 < NF) ? g_A[t*NF*NF + (2*p+1)*NF + n] : 0.f;
        uint32_t hi, lo;
        splitpk(w0, w1, hi, lo);
        g_APH[i] = hi;
        g_APL[i] = lo;
    }
}

// ---------------- prep 5: gate_w -> split pairs ---------------------------
__global__ void prep_gp(const float* __restrict__ gate_w) {
    int i = blockIdx.x * 256 + threadIdx.x;   // c*1280 + p
    if (i < NF * 1280) {
        int c = i / 1280, p = i - c*1280;
        float w0 = gate_w[(2*p)*NF + c];
        float w1 = gate_w[(2*p+1)*NF + c];
        uint32_t hi, lo;
        splitpk(w0, w1, hi, lo);
        g_GPH[i] = hi;
        g_GPL[i] = lo;
    }
}

// ---------------- kernel 1: full split-bf16 MMA forward -------------------
// smem (u32 words):
//  sXPH [24][136] @0      sXPL @3264        (x pairs, K=m, cols c*64+d)
//  sATH [48][28]  @6528   sATL @7872        (A^T pairs, current t)
//  sCPH [80][68]  @9216   sCPL @14656       (cat pairs)
//  sWPH [64][68]  @20096  sWPL @24448       (W pairs)
// total 28800 words = 115200 B/CTA -> 2 CTAs = 230400 B <= 228KiB
#define SMF_XPH 0
#define SMF_XPL 3264
#define SMF_ATH 6528
#define SMF_ATL 7872
#define SMF_CPH 9216
#define SMF_CPL 14656
#define SMF_WPH 20096
#define SMF_WPL 24448
#define SMF_WORDS 28800
#define SM_FWD_BYTES (SMF_WORDS*4)
__global__ __launch_bounds__(256, 2)
void k_forward(const float* __restrict__ x) {
    extern __shared__ uint32_t sw[];
    uint32_t* sXPH = sw + SMF_XPH;
    uint32_t* sXPL = sw + SMF_XPL;
    uint32_t* sATH = sw + SMF_ATH;
    uint32_t* sATL = sw + SMF_ATL;
    uint32_t* sCPH = sw + SMF_CPH;
    uint32_t* sCPL = sw + SMF_CPL;
    uint32_t* sWPH = sw + SMF_WPH;
    uint32_t* sWPL = sw + SMF_WPL;

    int tid  = threadIdx.x;
    int wid  = tid >> 5, lane = tid & 31;
    int g    = lane >> 2, tg = lane & 3;
    int b0   = blockIdx.x * CHUNK;
    const float* xb = x + (size_t)b0 * NF * DD;

    // ---- build x pair tiles (t-invariant): XP[p=m/2][c*64+d] ----
    for (int idx = tid; idx < 2560; idx += 256) {
        int p   = idx >> 7;          // 0..19
        int col = idx & 127;
        int c = col >> 6, d = col & 63;
        float x0 = __ldg(xb + c*2560 + (2*p)*64 + d);
        float x1 = __ldg(xb + c*2560 + (2*p+1)*64 + d);
        uint32_t h, l;
        splitpk(x0, x1, h, l);
        sXPH[p*136 + col] = h;
        sXPL[p*136 + col] = l;
    }
    // zero K-pad rows p = 20..23
    for (int idx = tid; idx < 544; idx += 256) {
        sXPH[20*136 + idx] = 0u;
        sXPL[20*136 + idx] = 0u;
    }

    for (int t = 0; t < TT; ++t) {
        // ---- stage A^T pairs (48x24 -> stride 28) ----
        for (int idx = tid; idx < 1152; idx += 256) {
            int n = idx / 24, p = idx - n*24;
            sATH[n*28 + p] = g_APH[t*1152 + idx];
            sATL[n*28 + p] = g_APL[t*1152 + idx];
        }
        // ---- stage W pairs ----
        for (int idx = tid; idx < 1024; idx += 256) {
            int p = idx >> 4, dq = (idx & 15) * 4;
            *(uint4*)(sWPH + p*68 + dq) = *(const uint4*)(g_WPH + t*4096 + p*64 + dq);
            *(uint4*)(sWPL + p*68 + dq) = *(const uint4*)(g_WPL + t*4096 + p*64 + dq);
        }
        // ---- cat lower half: x * s_lo -> pairs ----
        for (int idx = tid; idx < 1280; idx += 256) {
            int row = idx >> 4, q = idx & 15;
            int c = row / 40, n = row - c*40;
            float4 xv = __ldg((const float4*)(xb + c*2560 + n*64 + q*4));
            float4 sv = __ldg((const float4*)(g_S + t*NF*128 + n*128 + q*4));
            uint32_t h0, l0, h1, l1;
            splitpk(xv.x*sv.x, xv.y*sv.y, h0, l0);
            splitpk(xv.z*sv.z, xv.w*sv.w, h1, l1);
            *(uint2*)(sCPH + row*68 + q*2) = make_uint2(h0, h1);
            *(uint2*)(sCPL + row*68 + q*2) = make_uint2(l0, l1);
        }
        __syncthreads();

        // ---- phase A MMA: nei[48 x 128] = A^T[48 x 48k] @ xp[48k x 128] ----
        {
            float aacc[3][2][4];
            #pragma unroll
            for (int m = 0; m < 3; ++m)
                #pragma unroll
                for (int c2 = 0; c2 < 2; ++c2)
                    #pragma unroll
                    for (int j = 0; j < 4; ++j) aacc[m][c2][j] = 0.f;

            #pragma unroll
            for (int ks = 0; ks < 3; ++ks) {
                uint32_t bh0[2], bh1[2], bl0[2], bl1[2];
                #pragma unroll
                for (int c2 = 0; c2 < 2; ++c2) {
                    int colb = (wid*2 + c2)*8 + g;
                    bh0[c2] = sXPH[(ks*8 + tg)*136 + colb];
                    bh1[c2] = sXPH[(ks*8 + tg + 4)*136 + colb];
                    bl0[c2] = sXPL[(ks*8 + tg)*136 + colb];
                    bl1[c2] = sXPL[(ks*8 + tg + 4)*136 + colb];
                }
                #pragma unroll
                for (int mt = 0; mt < 3; ++mt) {
                    int ra = (mt*16 + g)*28 + ks*8 + tg;
                    int rb = (mt*16 + 8 + g)*28 + ks*8 + tg;
                    uint32_t a0h = sATH[ra], a1h = sATH[rb], a2h = sATH[ra+4], a3h = sATH[rb+4];
                    uint32_t a0l = sATL[ra], a1l = sATL[rb], a2l = sATL[ra+4], a3l = sATL[rb+4];
                    #pragma unroll
                    for (int c2 = 0; c2 < 2; ++c2) {
                        mma_bf16(aacc[mt][c2], a0h, a1h, a2h, a3h, bh0[c2], bh1[c2]);
                        mma_bf16(aacc[mt][c2], a0h, a1h, a2h, a3h, bl0[c2], bl1[c2]);
                        mma_bf16(aacc[mt][c2], a0l, a1l, a2l, a3l, bh0[c2], bh1[c2]);
                    }
                }
            }

            // epilogue A: scale by s_hi, split, write cat upper half
            #pragma unroll
            for (int mt = 0; mt < 3; ++mt) {
                #pragma unroll
                for (int c2 = 0; c2 < 2; ++c2) {
                    int col = (wid*2 + c2)*8 + tg*2;
                    int c = col >> 6, d = col & 63;
                    int r0 = mt*16 + g;
                    if (r0 < NF) {
                        float2 sv = __ldg((const float2*)(g_S + t*NF*128 + r0*128 + 64 + d));
                        uint32_t h, l;
                        splitpk(aacc[mt][c2][0]*sv.x, aacc[mt][c2][1]*sv.y, h, l);
                        sCPH[(c*40 + r0)*68 + 32 + (d>>1)] = h;
                        sCPL[(c*40 + r0)*68 + 32 + (d>>1)] = l;
                    }
                    int r1 = mt*16 + 8 + g;
                    if (r1 < NF) {
                        float2 sv = __ldg((const float2*)(g_S + t*NF*128 + r1*128 + 64 + d));
                        uint32_t h, l;
                        splitpk(aacc[mt][c2][2]*sv.x, aacc[mt][c2][3]*sv.y, h, l);
                        sCPH[(c*40 + r1)*68 + 32 + (d>>1)] = h;
                        sCPL[(c*40 + r1)*68 + 32 + (d>>1)] = l;
                    }
                }
            }
        }
        __syncthreads();

        // ---- phase B MMA: h[80x64] = cat[80x128] @ W[128x64] ----
        {
            float acc[5][4];
            #pragma unroll
            for (int m = 0; m < 5; ++m)
                #pragma unroll
                for (int j = 0; j < 4; ++j) acc[m][j] = 0.f;

            #pragma unroll
            for (int s = 0; s < 8; ++s) {
                int pb0 = (8*s + tg)*68     + wid*8 + g;
                int pb1 = (8*s + tg + 4)*68 + wid*8 + g;
                uint32_t b0h = sWPH[pb0], b1h = sWPH[pb1];
                uint32_t b0l = sWPL[pb0], b1l = sWPL[pb1];
                #pragma unroll
                for (int m = 0; m < 5; ++m) {
                    int ra = (m*16 + g)*68     + 8*s + tg;
                    int rb = (m*16 + 8 + g)*68 + 8*s + tg;
                    uint32_t a0h = sCPH[ra], a1h = sCPH[rb], a2h = sCPH[ra+4], a3h = sCPH[rb+4];
                    uint32_t a0l = sCPL[ra], a1l = sCPL[rb], a2l = sCPL[ra+4], a3l = sCPL[rb+4];
                    mma_bf16(acc[m], a0h, a1h, a2h, a3h, b0h, b1h);
                    mma_bf16(acc[m], a0h, a1h, a2h, a3h, b0l, b1l);
                    mma_bf16(acc[m], a0l, a1l, a2l, a3l, b0h, b1h);
                }
            }

            // epilogue: +bias, split and store h pairs
            int d = wid*8 + tg*2;
            int pq = wid*4 + tg;
            #pragma unroll
            for (int m = 0; m < 5; ++m) {
                int r0 = m*16 + g;
                int r1 = r0 + 8;
                int c0r = r0 / 40, n0 = r0 - c0r*40;
                float2 bp0 = *(const float2*)(g_BP + t*2560 + n0*64 + d);
                uint32_t h0, l0;
                splitpk(acc[m][0] + bp0.x, acc[m][1] + bp0.y, h0, l0);
                size_t row0i = (size_t)((b0 + c0r)*TT + t) * 1280 + n0*32 + pq;
                g_HH[row0i] = h0; g_HL[row0i] = l0;

                int c1r = r1 / 40, n1 = r1 - c1r*40;
                float2 bp1 = *(const float2*)(g_BP + t*2560 + n1*64 + d);
                uint32_t h1, l1;
                splitpk(acc[m][2] + bp1.x, acc[m][3] + bp1.y, h1, l1);
                size_t row1i = (size_t)((b0 + c1r)*TT + t) * 1280 + n1*32 + pq;
                g_HH[row1i] = h1; g_HL[row1i] = l1;
            }
        }
        __syncthreads();
    }
}

// ---------------- kernel 2: gate via split-bf16 mma + softmax + pool -----
#define ASTR 36
#define AH_W (64*ASTR)
#define BH_W (NF*ASTR)
#define BUF_W (2*AH_W + 2*BH_W)
#define GSM_WORDS (2*BUF_W)
__device__ __forceinline__ void gate_issue_chunk(uint32_t bufb, int row0, int ck, int tid) {
    #pragma unroll
    for (int q = 0; q < 4; ++q) {
        int idx = tid + q*128;
        int r = idx >> 3, j = idx & 7;
        uint32_t dst = bufb + (uint32_t)(r*ASTR + j*4)*4u;
        cpa16(dst, g_HH + (size_t)(row0 + r)*1280 + ck*32 + j*4);
        cpa16(dst + AH_W*4u, g_HL + (size_t)(row0 + r)*1280 + ck*32 + j*4);
    }
    #pragma unroll
    for (int q = 0; q < 3; ++q) {
        int idx = tid + q*128;
        if (idx < 320) {
            int c = idx >> 3, j = idx & 7;
            uint32_t dst = bufb + (uint32_t)(2*AH_W + c*ASTR + j*4)*4u;
            cpa16(dst, g_GPH + c*1280 + ck*32 + j*4);
            cpa16(dst + BH_W*4u, g_GPL + c*1280 + ck*32 + j*4);
        }
    }
    CPA_COMMIT();
}
__global__ __launch_bounds__(128)
void k_gate(const float* __restrict__ gate_b, float* __restrict__ out) {
    extern __shared__ uint32_t gw[];
    uint32_t gb = smem_u32(gw);
    int tid  = threadIdx.x;
    int wid  = tid >> 5, lane = tid & 31;
    int g    = lane >> 2, tg = lane & 3;
    int row0 = blockIdx.x * 64;

    float acc[5][4];
    #pragma unroll
    for (int m = 0; m < 5; ++m)
        #pragma unroll
        for (int j = 0; j < 4; ++j) acc[m][j] = 0.f;

    gate_issue_chunk(gb, row0, 0, tid);

    for (int ck = 0; ck < 40; ++ck) {
        int cur = ck & 1;
        bool more = (ck + 1) < 40;
        if (more) gate_issue_chunk(gb + (cur^1)*BUF_W*4u, row0, ck + 1, tid);
        if (more) { CPA_WAIT(1); } else { CPA_WAIT(0); }
        __syncthreads();

        const uint32_t* Ah = gw + cur*BUF_W;
        const uint32_t* Al = Ah + AH_W;
        const uint32_t* Bh = Ah + 2*AH_W;
        const uint32_t* Bl = Bh + BH_W;

        #pragma unroll
        for (int ks = 0; ks < 4; ++ks) {
            int ko = ks*8;
            int ra = (wid*16 + g)*ASTR + ko + tg;
            int rb = (wid*16 + 8 + g)*ASTR + ko + tg;
            uint32_t a0h = Ah[ra], a1h = Ah[rb], a2h = Ah[ra+4], a3h = Ah[rb+4];
            uint32_t a0l = Al[ra], a1l = Al[rb], a2l = Al[ra+4], a3l = Al[rb+4];
            #pragma unroll
            for (int nt = 0; nt < 5; ++nt) {
                int pb = (nt*8 + g)*ASTR + ko + tg;
                uint32_t b0h = Bh[pb], b1h = Bh[pb+4];
                uint32_t b0l = Bl[pb], b1l = Bl[pb+4];
                mma_bf16(acc[nt], a0h, a1h, a2h, a3h, b0h, b1h);
                mma_bf16(acc[nt], a0h, a1h, a2h, a3h, b0l, b1l);
                mma_bf16(acc[nt], a0l, a1l, a2l, a3l, b0h, b1h);
            }
        }
        __syncthreads();
    }

    float* sL = (float*)gw;
    #pragma unroll
    for (int nt = 0; nt < 5; ++nt) {
        int col = nt*8 + tg*2;
        float b0 = __ldg(gate_b + col);
        float b1 = __ldg(gate_b + col + 1);
        sL[(wid*16 + g)*41 + col]         = acc[nt][0] + b0;
        sL[(wid*16 + g)*41 + col + 1]     = acc[nt][1] + b1;
        sL[(wid*16 + 8 + g)*41 + col]     = acc[nt][2] + b0;
        sL[(wid*16 + 8 + g)*41 + col + 1] = acc[nt][3] + b1;
    }
    __syncthreads();

    if (tid < 64) {
        float* lp = sL + tid*41;
        float mx = -1e30f;
        #pragma unroll 8
        for (int n = 0; n < NF; ++n) mx = fmaxf(mx, lp[n]);
        float se = 0.f;
        #pragma unroll 8
        for (int n = 0; n < NF; ++n) se += expf(lp[n] - mx);
        float inv = 1.f / se;
        #pragma unroll 8
        for (int n = 0; n < NF; ++n) lp[n] = expf(lp[n] - mx) * inv;
    }
    __syncthreads();

    {
        int row = tid >> 1;
        int pb  = (tid & 1) * 16;
        const uint32_t* hh = g_HH + (size_t)(row0 + row)*1280 + pb;
        const uint32_t* hl = g_HL + (size_t)(row0 + row)*1280 + pb;
        const float* wp = sL + row*41;
        float2 a2[16];
        #pragma unroll
        for (int q = 0; q < 16; ++q) a2[q] = make_float2(0.f, 0.f);
        #pragma unroll 4
        for (int n = 0; n < NF; ++n) {
            float wv = wp[n];
            #pragma unroll
            for (int q4 = 0; q4 < 4; ++q4) {
                uint4 hv = *(const uint4*)(hh + n*32 + q4*4);
                uint4 lv = *(const uint4*)(hl + n*32 + q4*4);
                float2 f0 = rec2(hv.x, lv.x), f1 = rec2(hv.y, lv.y);
                float2 f2 = rec2(hv.z, lv.z), f3 = rec2(hv.w, lv.w);
                a2[q4*4+0].x += wv*f0.x; a2[q4*4+0].y += wv*f0.y;
                a2[q4*4+1].x += wv*f1.x; a2[q4*4+1].y += wv*f1.y;
                a2[q4*4+2].x += wv*f2.x; a2[q4*4+2].y += wv*f2.y;
                a2[q4*4+3].x += wv*f3.x; a2[q4*4+3].y += wv*f3.y;
            }
        }
        float* op = out + (size_t)(row0 + row)*64 + (tid & 1)*32;
        #pragma unroll
        for (int q = 0; q < 8; ++q)
            *(float4*)(op + q*4) = make_float4(a2[q*2].x, a2[q*2].y, a2[q*2+1].x, a2[q*2+1].y);
    }
}

// ---------------- launcher ------------------------------------------------
extern "C" void kernel_launch(void* const* d_in, const int* in_sizes, int n_in,
                              void* d_out, int out_size) {
    const float* x        = (const float*)d_in[0];
    const float* masker   = (const float*)d_in[1];
    const float* ln_gamma = (const float*)d_in[2];
    const float* ln_beta  = (const float*)d_in[3];
    const float* gnn_w    = (const float*)d_in[4];
    const float* gnn_b    = (const float*)d_in[5];
    const float* bn_gamma = (const float*)d_in[6];
    const float* bn_beta  = (const float*)d_in[7];
    const float* bn_mean  = (const float*)d_in[8];
    const float* bn_var   = (const float*)d_in[9];
    const float* gate_w   = (const float*)d_in[10];
    const float* gate_b   = (const float*)d_in[11];
    float* out = (float*)d_out;

    cudaFuncSetAttribute(k_forward, cudaFuncAttributeMaxDynamicSharedMemorySize,
                         SM_FWD_BYTES);
    cudaFuncSetAttribute(k_gate, cudaFuncAttributeMaxDynamicSharedMemorySize,
                         GSM_WORDS * (int)sizeof(uint32_t));

    prep_adj<<<2, 256>>>(masker, ln_gamma, ln_beta);
    prep_ap<<<(TT*48*24 + 255)/256, 256>>>();
    prep_sbp<<<80, 128>>>(bn_gamma, bn_beta, bn_mean, bn_var, gnn_w, gnn_b);
    prep_wp<<<(TT*64*64 + 255)/256, 256>>>(gnn_w);
    prep_gp<<<(NF*1280 + 255)/256, 256>>>(gate_w);
    k_forward<<<BSZ / CHUNK, 256, SM_FWD_BYTES>>>(x);
    k_gate<<<BSZ * TT / 64, 128, GSM_WORDS * sizeof(uint32_t)>>>(gate_b, out);
}

// round 11
// speedup vs baseline: 2.4280x; 1.0367x over previous
#include <cuda_runtime.h>
#include <cuda_bf16.h>
#include <math.h>
#include <stdint.h>

#define BSZ   8192
#define TT    2
#define NF    40
#define DD    64
#define FEPS  1e-5f
#define CHUNK 2

typedef unsigned long long u64;

// ---- split-bf16: (a,b) -> hi pair + residual pair ----
__device__ __forceinline__ void splitpk(float a, float b, uint32_t& hi, uint32_t& lo) {
    __nv_bfloat162 h = __floats2bfloat162_rn(a, b);
    float ra = a - __bfloat162float(h.x);
    float rb = b - __bfloat162float(h.y);
    __nv_bfloat162 l = __floats2bfloat162_rn(ra, rb);
    hi = *reinterpret_cast<uint32_t*>(&h);
    lo = *reinterpret_cast<uint32_t*>(&l);
}
__device__ __forceinline__ float2 rec2(uint32_t h, uint32_t l) {
    float2 hf = __bfloat1622float2(*reinterpret_cast<__nv_bfloat162*>(&h));
    float2 lf = __bfloat1622float2(*reinterpret_cast<__nv_bfloat162*>(&l));
    return make_float2(hf.x + lf.x, hf.y + lf.y);
}

// ---- legacy tensor core mma (sm_80+) ----
__device__ __forceinline__ void mma_bf16(float* d,
    uint32_t a0, uint32_t a1, uint32_t a2, uint32_t a3,
    uint32_t b0, uint32_t b1) {
    asm volatile(
        "mma.sync.aligned.m16n8k16.row.col.f32.bf16.bf16.f32 "
        "{%0,%1,%2,%3}, {%4,%5,%6,%7}, {%8,%9}, {%0,%1,%2,%3};"
        : "+f"(d[0]), "+f"(d[1]), "+f"(d[2]), "+f"(d[3])
        : "r"(a0), "r"(a1), "r"(a2), "r"(a3), "r"(b0), "r"(b1));
}

// ---- ldmatrix x4 (sm_75+): fills full m16k16 A fragment in one op ----
__device__ __forceinline__ void ldsm4(uint32_t& r0, uint32_t& r1,
                                      uint32_t& r2, uint32_t& r3, uint32_t addr) {
    asm volatile("ldmatrix.sync.aligned.m8n8.x4.shared.b16 {%0,%1,%2,%3}, [%4];"
        : "=r"(r0), "=r"(r1), "=r"(r2), "=r"(r3) : "r"(addr));
}

// ---- cp.async (sm_80+) ----
__device__ __forceinline__ uint32_t smem_u32(const void* p) {
    uint32_t a;
    asm("{ .reg .u64 t; cvta.to.shared.u64 t, %1; cvt.u32.u64 %0, t; }" : "=r"(a) : "l"(p));
    return a;
}
__device__ __forceinline__ void cpa16(uint32_t dst, const void* src) {
    asm volatile("cp.async.cg.shared.global [%0], [%1], 16;" :: "r"(dst), "l"(src));
}
#define CPA_COMMIT() asm volatile("cp.async.commit_group;" ::: "memory")
#define CPA_WAIT(n)  asm volatile("cp.async.wait_group %0;" :: "n"(n) : "memory")

// ---------------- device scratch ----------------
__device__ float g_A [TT*NF*NF];
__device__ float g_S [TT*NF*128];
__device__ float g_BP[TT*NF*DD];
__device__ uint32_t g_WPH[TT*64*64];
__device__ uint32_t g_WPL[TT*64*64];
__device__ uint32_t g_APH[TT*48*24];
__device__ uint32_t g_APL[TT*48*24];
__device__ uint32_t g_HH[(size_t)BSZ*TT*1280];
__device__ uint32_t g_HL[(size_t)BSZ*TT*1280];
__device__ uint32_t g_GPH[NF*1280];
__device__ uint32_t g_GPL[NF*1280];

// ---------------- prep 1: adjacency -> LN -> mask -> softmax -> A --------
__global__ void prep_adj(const float* __restrict__ masker,
                         const float* __restrict__ ln_gamma,
                         const float* __restrict__ ln_beta) {
    int t = blockIdx.x;
    __shared__ float sadj[NF*NF];
    int tid = threadIdx.x;
    const float* mk = masker + (size_t)t * 3 * NF * NF;
    for (int i = tid; i < NF*NF; i += blockDim.x) {
        float p = mk[i] * mk[NF*NF + i] * mk[2*NF*NF + i];
        sadj[i] = p > 0.f ? p : 0.f;
    }
    __syncthreads();
    if (tid < NF) {
        int j = tid;
        float sum = 0.f, sq = 0.f;
        for (int i = 0; i < NF; ++i) { float a = sadj[i*NF + j]; sum += a; sq += a*a; }
        float mu  = sum * (1.f/NF);
        float var = sq * (1.f/NF) - mu*mu;
        float rs  = rsqrtf(var + FEPS);
        float xm[NF];
        float mx = -1e30f;
        for (int i = 0; i < NF; ++i) {
            float a   = sadj[i*NF + j];
            float msk = (a != 0.f) ? 1.f : 0.f;
            float v   = (a - mu) * rs * ln_gamma[i] + ln_beta[i];
            v += (1.f - msk) * (-1e9f);
            if (i == j) v += 1.f;
            xm[i] = v;
            mx = fmaxf(mx, v);
        }
        float se = 0.f;
        for (int i = 0; i < NF; ++i) { xm[i] = expf(xm[i] - mx); se += xm[i]; }
        float inv = 1.f / se;
        for (int i = 0; i < NF; ++i) {
            float a   = sadj[i*NF + j];
            float msk = (a != 0.f) ? 1.f : 0.f;
            g_A[t*NF*NF + i*NF + j] = xm[i] * inv * msk;
        }
    }
}

// ---------------- prep 2: fold BN into scale s and bias b' ---------------
__global__ void prep_sbp(const float* __restrict__ bn_gamma,
                         const float* __restrict__ bn_beta,
                         const float* __restrict__ bn_mean,
                         const float* __restrict__ bn_var,
                         const float* __restrict__ gnn_w,
                         const float* __restrict__ gnn_b) {
    int blk = blockIdx.x;          // t*40 + n
    int t = blk / NF, n = blk - t*NF;
    __shared__ float so[128];
    int tid = threadIdx.x;
    int F = blk*128 + tid;
    float s = bn_gamma[F] * rsqrtf(bn_var[F] + FEPS);
    float o = bn_beta[F] - bn_mean[F] * s;
    g_S[blk*128 + tid] = s;
    so[tid] = o;
    __syncthreads();
    if (tid < DD) {
        float acc = gnn_b[t*NF*DD + n*DD + tid];
        #pragma unroll 8
        for (int f = 0; f < 128; ++f)
            acc += so[f] * gnn_w[t*128*DD + f*DD + tid];
        g_BP[blk*DD + tid] = acc;
    }
}

// ---------------- prep 3: W -> split pairs --------------------------------
__global__ void prep_wp(const float* __restrict__ gnn_w) {
    int i = blockIdx.x * 256 + threadIdx.x;
    if (i < TT*64*64) {
        int t = i >> 12, r = i & 4095;
        int p = r >> 6, d = r & 63;
        float w0 = gnn_w[t*8192 + (2*p)*64 + d];
        float w1 = gnn_w[t*8192 + (2*p+1)*64 + d];
        uint32_t hi, lo;
        splitpk(w0, w1, hi, lo);
        g_WPH[i] = hi;
        g_WPL[i] = lo;
    }
}

// ---------------- prep 4: A^T -> split pairs (padded 48x24) --------------
__global__ void prep_ap() {
    int i = blockIdx.x * 256 + threadIdx.x;
    if (i < TT*48*24) {
        int t = i / 1152, r = i - t*1152;
        int n = r / 24, p = r - n*24;
        float w0 = (n < NF && 2*p   < NF) ? g_A[t*NF*NF + (2*p)*NF + n]   : 0.f;
        float w1 = (n < NF && 2*p+1 < NF) ? g_A[t*NF*NF + (2*p+1)*NF + n] : 0.f;
        uint32_t hi, lo;
        splitpk(w0, w1, hi, lo);
        g_APH[i] = hi;
        g_APL[i] = lo;
    }
}

// ---------------- prep 5: gate_w -> split pairs ---------------------------
__global__ void prep_gp(const float* __restrict__ gate_w) {
    int i = blockIdx.x * 256 + threadIdx.x;
    if (i < NF * 1280) {
        int c = i / 1280, p = i - c*1280;
        float w0 = gate_w[(2*p)*NF + c];
        float w1 = gate_w[(2*p+1)*NF + c];
        uint32_t hi, lo;
        splitpk(w0, w1, hi, lo);
        g_GPH[i] = hi;
        g_GPL[i] = lo;
    }
}

// ---------------- kernel 1: full split-bf16 MMA forward -------------------
#define SMF_XPH 0
#define SMF_XPL 3264
#define SMF_ATH 6528
#define SMF_ATL 7872
#define SMF_CPH 9216
#define SMF_CPL 14656
#define SMF_WPH 20096
#define SMF_WPL 24448
#define SMF_WORDS 28800
#define SM_FWD_BYTES (SMF_WORDS*4)
__global__ __launch_bounds__(256, 2)
void k_forward(const float* __restrict__ x) {
    extern __shared__ uint32_t sw[];
    uint32_t* sXPH = sw + SMF_XPH;
    uint32_t* sXPL = sw + SMF_XPL;
    uint32_t* sATH = sw + SMF_ATH;
    uint32_t* sATL = sw + SMF_ATL;
    uint32_t* sCPH = sw + SMF_CPH;
    uint32_t* sCPL = sw + SMF_CPL;
    uint32_t* sWPH = sw + SMF_WPH;
    uint32_t* sWPL = sw + SMF_WPL;
    uint32_t sbase = smem_u32(sw);

    int tid  = threadIdx.x;
    int wid  = tid >> 5, lane = tid & 31;
    int g    = lane >> 2, tg = lane & 3;
    uint32_t lrow = lane & 15;
    uint32_t lcol = (lane >> 4) << 2;   // 0 or 4 (pair units)
    int b0   = blockIdx.x * CHUNK;
    const float* xb = x + (size_t)b0 * NF * DD;

    // ---- build x pair tiles (t-invariant): XP[p=m/2][c*64+d] ----
    for (int idx = tid; idx < 2560; idx += 256) {
        int p   = idx >> 7;
        int col = idx & 127;
        int c = col >> 6, d = col & 63;
        float x0 = __ldg(xb + c*2560 + (2*p)*64 + d);
        float x1 = __ldg(xb + c*2560 + (2*p+1)*64 + d);
        uint32_t h, l;
        splitpk(x0, x1, h, l);
        sXPH[p*136 + col] = h;
        sXPL[p*136 + col] = l;
    }
    for (int idx = tid; idx < 544; idx += 256) {
        sXPH[20*136 + idx] = 0u;
        sXPL[20*136 + idx] = 0u;
    }

    for (int t = 0; t < TT; ++t) {
        // ---- stage A^T pairs (48x24 -> stride 28) ----
        for (int idx = tid; idx < 1152; idx += 256) {
            int n = idx / 24, p = idx - n*24;
            sATH[n*28 + p] = g_APH[t*1152 + idx];
            sATL[n*28 + p] = g_APL[t*1152 + idx];
        }
        // ---- stage W pairs ----
        for (int idx = tid; idx < 1024; idx += 256) {
            int p = idx >> 4, dq = (idx & 15) * 4;
            *(uint4*)(sWPH + p*68 + dq) = *(const uint4*)(g_WPH + t*4096 + p*64 + dq);
            *(uint4*)(sWPL + p*68 + dq) = *(const uint4*)(g_WPL + t*4096 + p*64 + dq);
        }
        // ---- cat lower half: x * s_lo -> pairs ----
        for (int idx = tid; idx < 1280; idx += 256) {
            int row = idx >> 4, q = idx & 15;
            int c = row / 40, n = row - c*40;
            float4 xv = __ldg((const float4*)(xb + c*2560 + n*64 + q*4));
            float4 sv = __ldg((const float4*)(g_S + t*NF*128 + n*128 + q*4));
            uint32_t h0, l0, h1, l1;
            splitpk(xv.x*sv.x, xv.y*sv.y, h0, l0);
            splitpk(xv.z*sv.z, xv.w*sv.w, h1, l1);
            *(uint2*)(sCPH + row*68 + q*2) = make_uint2(h0, h1);
            *(uint2*)(sCPL + row*68 + q*2) = make_uint2(l0, l1);
        }
        __syncthreads();

        // ---- phase A MMA: nei[48 x 128] = A^T[48 x 48k] @ xp[48k x 128] ----
        {
            float aacc[3][2][4];
            #pragma unroll
            for (int m = 0; m < 3; ++m)
                #pragma unroll
                for (int c2 = 0; c2 < 2; ++c2)
                    #pragma unroll
                    for (int j = 0; j < 4; ++j) aacc[m][c2][j] = 0.f;

            #pragma unroll
            for (int ks = 0; ks < 3; ++ks) {
                uint32_t bh0[2], bh1[2], bl0[2], bl1[2];
                #pragma unroll
                for (int c2 = 0; c2 < 2; ++c2) {
                    int colb = (wid*2 + c2)*8 + g;
                    bh0[c2] = sXPH[(ks*8 + tg)*136 + colb];
                    bh1[c2] = sXPH[(ks*8 + tg + 4)*136 + colb];
                    bl0[c2] = sXPL[(ks*8 + tg)*136 + colb];
                    bl1[c2] = sXPL[(ks*8 + tg + 4)*136 + colb];
                }
                #pragma unroll
                for (int mt = 0; mt < 3; ++mt) {
                    uint32_t ah = sbase + (SMF_ATH + (mt*16 + lrow)*28 + ks*8 + lcol)*4u;
                    uint32_t a0h, a1h, a2h, a3h, a0l, a1l, a2l, a3l;
                    ldsm4(a0h, a1h, a2h, a3h, ah);
                    ldsm4(a0l, a1l, a2l, a3l, ah + (SMF_ATL - SMF_ATH)*4u);
                    #pragma unroll
                    for (int c2 = 0; c2 < 2; ++c2) {
                        mma_bf16(aacc[mt][c2], a0h, a1h, a2h, a3h, bh0[c2], bh1[c2]);
                        mma_bf16(aacc[mt][c2], a0h, a1h, a2h, a3h, bl0[c2], bl1[c2]);
                        mma_bf16(aacc[mt][c2], a0l, a1l, a2l, a3l, bh0[c2], bh1[c2]);
                    }
                }
            }

            // epilogue A: scale by s_hi, split, write cat upper half
            #pragma unroll
            for (int mt = 0; mt < 3; ++mt) {
                #pragma unroll
                for (int c2 = 0; c2 < 2; ++c2) {
                    int col = (wid*2 + c2)*8 + tg*2;
                    int c = col >> 6, d = col & 63;
                    int r0 = mt*16 + g;
                    if (r0 < NF) {
                        float2 sv = __ldg((const float2*)(g_S + t*NF*128 + r0*128 + 64 + d));
                        uint32_t h, l;
                        splitpk(aacc[mt][c2][0]*sv.x, aacc[mt][c2][1]*sv.y, h, l);
                        sCPH[(c*40 + r0)*68 + 32 + (d>>1)] = h;
                        sCPL[(c*40 + r0)*68 + 32 + (d>>1)] = l;
                    }
                    int r1 = mt*16 + 8 + g;
                    if (r1 < NF) {
                        float2 sv = __ldg((const float2*)(g_S + t*NF*128 + r1*128 + 64 + d));
                        uint32_t h, l;
                        splitpk(aacc[mt][c2][2]*sv.x, aacc[mt][c2][3]*sv.y, h, l);
                        sCPH[(c*40 + r1)*68 + 32 + (d>>1)] = h;
                        sCPL[(c*40 + r1)*68 + 32 + (d>>1)] = l;
                    }
                }
            }
        }
        __syncthreads();

        // ---- phase B MMA: h[80x64] = cat[80x128] @ W[128x64] ----
        {
            float acc[5][4];
            #pragma unroll
            for (int m = 0; m < 5; ++m)
                #pragma unroll
                for (int j = 0; j < 4; ++j) acc[m][j] = 0.f;

            #pragma unroll
            for (int s = 0; s < 8; ++s) {
                int pb0 = (8*s + tg)*68     + wid*8 + g;
                int pb1 = (8*s + tg + 4)*68 + wid*8 + g;
                uint32_t b0h = sWPH[pb0], b1h = sWPH[pb1];
                uint32_t b0l = sWPL[pb0], b1l = sWPL[pb1];
                #pragma unroll
                for (int m = 0; m < 5; ++m) {
                    uint32_t ah = sbase + (SMF_CPH + (m*16 + lrow)*68 + 8*s + lcol)*4u;
                    uint32_t a0h, a1h, a2h, a3h, a0l, a1l, a2l, a3l;
                    ldsm4(a0h, a1h, a2h, a3h, ah);
                    ldsm4(a0l, a1l, a2l, a3l, ah + (SMF_CPL - SMF_CPH)*4u);
                    mma_bf16(acc[m], a0h, a1h, a2h, a3h, b0h, b1h);
                    mma_bf16(acc[m], a0h, a1h, a2h, a3h, b0l, b1l);
                    mma_bf16(acc[m], a0l, a1l, a2l, a3l, b0h, b1h);
                }
            }

            // epilogue: +bias, split and store h pairs
            int d = wid*8 + tg*2;
            int pq = wid*4 + tg;
            #pragma unroll
            for (int m = 0; m < 5; ++m) {
                int r0 = m*16 + g;
                int r1 = r0 + 8;
                int c0r = r0 / 40, n0 = r0 - c0r*40;
                float2 bp0 = *(const float2*)(g_BP + t*2560 + n0*64 + d);
                uint32_t h0, l0;
                splitpk(acc[m][0] + bp0.x, acc[m][1] + bp0.y, h0, l0);
                size_t row0i = (size_t)((b0 + c0r)*TT + t) * 1280 + n0*32 + pq;
                g_HH[row0i] = h0; g_HL[row0i] = l0;

                int c1r = r1 / 40, n1 = r1 - c1r*40;
                float2 bp1 = *(const float2*)(g_BP + t*2560 + n1*64 + d);
                uint32_t h1, l1;
                splitpk(acc[m][2] + bp1.x, acc[m][3] + bp1.y, h1, l1);
                size_t row1i = (size_t)((b0 + c1r)*TT + t) * 1280 + n1*32 + pq;
                g_HH[row1i] = h1; g_HL[row1i] = l1;
            }
        }
        __syncthreads();
    }
}

// ---------------- kernel 2: gate via split-bf16 mma + softmax + pool -----
#define ASTR 36
#define AH_W (64*ASTR)
#define BH_W (NF*ASTR)
#define BUF_W (2*AH_W + 2*BH_W)
#define GSM_WORDS (2*BUF_W)
__device__ __forceinline__ void gate_issue_chunk(uint32_t bufb, int row0, int ck, int tid) {
    #pragma unroll
    for (int q = 0; q < 4; ++q) {
        int idx = tid + q*128;
        int r = idx >> 3, j = idx & 7;
        uint32_t dst = bufb + (uint32_t)(r*ASTR + j*4)*4u;
        cpa16(dst, g_HH + (size_t)(row0 + r)*1280 + ck*32 + j*4);
        cpa16(dst + AH_W*4u, g_HL + (size_t)(row0 + r)*1280 + ck*32 + j*4);
    }
    #pragma unroll
    for (int q = 0; q < 3; ++q) {
        int idx = tid + q*128;
        if (idx < 320) {
            int c = idx >> 3, j = idx & 7;
            uint32_t dst = bufb + (uint32_t)(2*AH_W + c*ASTR + j*4)*4u;
            cpa16(dst, g_GPH + c*1280 + ck*32 + j*4);
            cpa16(dst + BH_W*4u, g_GPL + c*1280 + ck*32 + j*4);
        }
    }
    CPA_COMMIT();
}
__global__ __launch_bounds__(128)
void k_gate(const float* __restrict__ gate_b, float* __restrict__ out) {
    extern __shared__ uint32_t gw[];
    uint32_t gb = smem_u32(gw);
    int tid  = threadIdx.x;
    int wid  = tid >> 5, lane = tid & 31;
    int g    = lane >> 2, tg = lane & 3;
    uint32_t lrow = lane & 15;
    uint32_t lcol = (lane >> 4) << 2;
    int row0 = blockIdx.x * 64;

    float acc[5][4];
    #pragma unroll
    for (int m = 0; m < 5; ++m)
        #pragma unroll
        for (int j = 0; j < 4; ++j) acc[m][j] = 0.f;

    gate_issue_chunk(gb, row0, 0, tid);

    for (int ck = 0; ck < 40; ++ck) {
        int cur = ck & 1;
        bool more = (ck + 1) < 40;
        if (more) gate_issue_chunk(gb + (cur^1)*BUF_W*4u, row0, ck + 1, tid);
        if (more) { CPA_WAIT(1); } else { CPA_WAIT(0); }
        __syncthreads();

        const uint32_t* Bh = gw + cur*BUF_W + 2*AH_W;
        const uint32_t* Bl = Bh + BH_W;
        uint32_t abase = gb + (uint32_t)(cur*BUF_W)*4u;

        #pragma unroll
        for (int ks = 0; ks < 4; ++ks) {
            int ko = ks*8;
            uint32_t ah = abase + ((wid*16 + lrow)*ASTR + ko + lcol)*4u;
            uint32_t a0h, a1h, a2h, a3h, a0l, a1l, a2l, a3l;
            ldsm4(a0h, a1h, a2h, a3h, ah);
            ldsm4(a0l, a1l, a2l, a3l, ah + AH_W*4u);
            #pragma unroll
            for (int nt = 0; nt < 5; ++nt) {
                int pb = (nt*8 + g)*ASTR + ko + tg;
                uint32_t b0h = Bh[pb], b1h = Bh[pb+4];
                uint32_t b0l = Bl[pb], b1l = Bl[pb+4];
                mma_bf16(acc[nt], a0h, a1h, a2h, a3h, b0h, b1h);
                mma_bf16(acc[nt], a0h, a1h, a2h, a3h, b0l, b1l);
                mma_bf16(acc[nt], a0l, a1l, a2l, a3l, b0h, b1h);
            }
        }
        __syncthreads();
    }

    float* sL = (float*)gw;
    #pragma unroll
    for (int nt = 0; nt < 5; ++nt) {
        int col = nt*8 + tg*2;
        float b0 = __ldg(gate_b + col);
        float b1 = __ldg(gate_b + col + 1);
        sL[(wid*16 + g)*41 + col]         = acc[nt][0] + b0;
        sL[(wid*16 + g)*41 + col + 1]     = acc[nt][1] + b1;
        sL[(wid*16 + 8 + g)*41 + col]     = acc[nt][2] + b0;
        sL[(wid*16 + 8 + g)*41 + col + 1] = acc[nt][3] + b1;
    }
    __syncthreads();

    if (tid < 64) {
        float* lp = sL + tid*41;
        float mx = -1e30f;
        #pragma unroll 8
        for (int n = 0; n < NF; ++n) mx = fmaxf(mx, lp[n]);
        float se = 0.f;
        #pragma unroll 8
        for (int n = 0; n < NF; ++n) se += expf(lp[n] - mx);
        float inv = 1.f / se;
        #pragma unroll 8
        for (int n = 0; n < NF; ++n) lp[n] = expf(lp[n] - mx) * inv;
    }
    __syncthreads();

    {
        int row = tid >> 1;
        int pb  = (tid & 1) * 16;
        const uint32_t* hh = g_HH + (size_t)(row0 + row)*1280 + pb;
        const uint32_t* hl = g_HL + (size_t)(row0 + row)*1280 + pb;
        const float* wp = sL + row*41;
        float2 a2[16];
        #pragma unroll
        for (int q = 0; q < 16; ++q) a2[q] = make_float2(0.f, 0.f);
        #pragma unroll 4
        for (int n = 0; n < NF; ++n) {
            float wv = wp[n];
            #pragma unroll
            for (int q4 = 0; q4 < 4; ++q4) {
                uint4 hv = *(const uint4*)(hh + n*32 + q4*4);
                uint4 lv = *(const uint4*)(hl + n*32 + q4*4);
                float2 f0 = rec2(hv.x, lv.x), f1 = rec2(hv.y, lv.y);
                float2 f2 = rec2(hv.z, lv.z), f3 = rec2(hv.w, lv.w);
                a2[q4*4+0].x += wv*f0.x; a2[q4*4+0].y += wv*f0.y;
                a2[q4*4+1].x += wv*f1.x; a2[q4*4+1].y += wv*f1.y;
                a2[q4*4+2].x += wv*f2.x; a2[q4*4+2].y += wv*f2.y;
                a2[q4*4+3].x += wv*f3.x; a2[q4*4+3].y += wv*f3.y;
            }
        }
        float* op = out + (size_t)(row0 + row)*64 + (tid & 1)*32;
        #pragma unroll
        for (int q = 0; q < 8; ++q)
            *(float4*)(op + q*4) = make_float4(a2[q*2].x, a2[q*2].y, a2[q*2+1].x, a2[q*2+1].y);
    }
}

// ---------------- launcher ------------------------------------------------
extern "C" void kernel_launch(void* const* d_in, const int* in_sizes, int n_in,
                              void* d_out, int out_size) {
    const float* x        = (const float*)d_in[0];
    const float* masker   = (const float*)d_in[1];
    const float* ln_gamma = (const float*)d_in[2];
    const float* ln_beta  = (const float*)d_in[3];
    const float* gnn_w    = (const float*)d_in[4];
    const float* gnn_b    = (const float*)d_in[5];
    const float* bn_gamma = (const float*)d_in[6];
    const float* bn_beta  = (const float*)d_in[7];
    const float* bn_mean  = (const float*)d_in[8];
    const float* bn_var   = (const float*)d_in[9];
    const float* gate_w   = (const float*)d_in[10];
    const float* gate_b   = (const float*)d_in[11];
    float* out = (float*)d_out;

    cudaFuncSetAttribute(k_forward, cudaFuncAttributeMaxDynamicSharedMemorySize,
                         SM_FWD_BYTES);
    cudaFuncSetAttribute(k_gate, cudaFuncAttributeMaxDynamicSharedMemorySize,
                         GSM_WORDS * (int)sizeof(uint32_t));

    prep_adj<<<2, 256>>>(masker, ln_gamma, ln_beta);
    prep_ap<<<(TT*48*24 + 255)/256, 256>>>();
    prep_sbp<<<80, 128>>>(bn_gamma, bn_beta, bn_mean, bn_var, gnn_w, gnn_b);
    prep_wp<<<(TT*64*64 + 255)/256, 256>>>(gnn_w);
    prep_gp<<<(NF*1280 + 255)/256, 256>>>(gate_w);
    k_forward<<<BSZ / CHUNK, 256, SM_FWD_BYTES>>>(x);
    k_gate<<<BSZ * TT / 64, 128, GSM_WORDS * sizeof(uint32_t)>>>(gate_b, out);
}